// round 4
// baseline (speedup 1.0000x reference)
#include <cuda_runtime.h>
#include <cstdint>

typedef unsigned long long ull;

#define B_   32
#define NH_  8
#define NN_  1024
#define NS_  21
#define NT_  1003
#define D_   128
#define KD_  16
#define HB_  (NH_*B_)

// NORM * log2(e) folded into query projections so softmax uses raw ex2.
#define QSCALE 0.36067376022224085f

// ---------------- scratch (device globals; no allocation allowed) ----------
__device__ float g_Qtt[HB_*NT_*KD_];
__device__ float g_Qts[HB_*NT_*KD_];
__device__ float g_Kc [HB_*NT_*KD_];
__device__ float g_Vc [HB_*NT_*KD_];
__device__ float g_Qst[HB_*NS_*KD_];
__device__ float g_Ks [HB_*NS_*KD_];
__device__ float g_Vs [HB_*NS_*KD_];
__device__ float g_heads[B_*NN_*NH_*KD_];   // layout [b][n][h][k]

// ---------------- f32x2 helpers (FFMA2: PTX-only, 2x fp32 throughput) ------
__device__ __forceinline__ ull pack2(float lo, float hi){
  ull r; asm("mov.b64 %0, {%1,%2};" : "=l"(r) : "f"(lo), "f"(hi)); return r;
}
__device__ __forceinline__ void unpack2(ull v, float& lo, float& hi){
  asm("mov.b64 {%0,%1}, %2;" : "=f"(lo), "=f"(hi) : "l"(v));
}
__device__ __forceinline__ ull ffma2(ull a, ull b, ull c){
  ull d; asm("fma.rn.f32x2 %0, %1, %2, %3;" : "=l"(d) : "l"(a), "l"(b), "l"(c)); return d;
}
__device__ __forceinline__ ull fmul2(ull a, ull b){
  ull d; asm("mul.rn.f32x2 %0, %1, %2;" : "=l"(d) : "l"(a), "l"(b)); return d;
}
__device__ __forceinline__ ull fadd2(ull a, ull b){
  ull d; asm("add.rn.f32x2 %0, %1, %2;" : "=l"(d) : "l"(a), "l"(b)); return d;
}
__device__ __forceinline__ float ex2f(float x){
  float r; asm("ex2.approx.f32 %0, %1;" : "=f"(r) : "f"(x)); return r;
}
__device__ __forceinline__ void cp_async16(void* s, const void* g){
  unsigned sa = (unsigned)__cvta_generic_to_shared(s);
  asm volatile("cp.async.cg.shared.global [%0], [%1], 16;" :: "r"(sa), "l"(g));
}
__device__ __forceinline__ void cp_commit(){ asm volatile("cp.async.commit_group;"); }
template<int N> __device__ __forceinline__ void cp_wait(){
  asm volatile("cp.async.wait_group %0;" :: "n"(N) : "memory");
}

// ====================== Kernel 1: token projections ========================
// Q_tt, Q_ts (from q tokens, scaled), K_c, V_c (from h tokens).
// Block = (token tile of 64, batch). f32x2 dot over d-pairs.
__global__ __launch_bounds__(256) void k_proj_tok(
    const float* __restrict__ q, const float* __restrict__ h,
    const float* __restrict__ Wqtt, const float* __restrict__ Wqts,
    const float* __restrict__ Wk, const float* __restrict__ Wv)
{
  extern __shared__ float sm[];
  float* sxq = sm;                  // 64*128
  float* sxh = sm + 64*D_;          // 64*128
  float* swt = sm + 2*64*D_;        // 16*132 (transposed weight, padded)

  int b  = blockIdx.y;
  int r0 = blockIdx.x * 64;
  int tid = threadIdx.x;

  #pragma unroll
  for (int i = 0; i < 8; i++){
    int idx = tid + i*256;              // float4 index, 2048 total
    int row = idx >> 5, d4 = idx & 31;
    int t = r0 + row; if (t > NT_-1) t = NT_-1;   // clamp (guarded on write)
    size_t goff = ((size_t)(b*NN_ + NS_ + t))*D_ + d4*4;
    ((float4*)(sxq + row*D_))[d4] = *(const float4*)(q + goff);
    ((float4*)(sxh + row*D_))[d4] = *(const float4*)(h + goff);
  }

  const float* Wp[4] = {Wqtt, Wqts, Wk, Wv};
  float* Dp[4]; Dp[0]=g_Qtt; Dp[1]=g_Qts; Dp[2]=g_Kc; Dp[3]=g_Vc;

  int rg = tid >> 4, kk = tid & 15;
  for (int p = 0; p < 4; p++){
    const float* src = (p < 2) ? sxq : sxh;
    float scale = (p < 2) ? QSCALE : 1.0f;
    for (int hh = 0; hh < NH_; hh++){
      __syncthreads();   // also covers initial x load
      const float* wp = Wp[p] + hh*D_*KD_;
      #pragma unroll
      for (int i = 0; i < 8; i++){
        int idx = tid + i*256;          // 2048 weight elems
        int d = idx >> 4, k2 = idx & 15;
        swt[k2*132 + d] = wp[idx] * scale;
      }
      __syncthreads();
      ull acc[4] = {0,0,0,0};
      #pragma unroll 4
      for (int d4 = 0; d4 < 32; d4++){
        ulonglong2 w = *(const ulonglong2*)(swt + kk*132 + d4*4);
        #pragma unroll
        for (int i = 0; i < 4; i++){
          ulonglong2 x = *(const ulonglong2*)(src + (rg*4 + i)*D_ + d4*4);
          acc[i] = ffma2(x.x, w.x, acc[i]);
          acc[i] = ffma2(x.y, w.y, acc[i]);
        }
      }
      float* dst = Dp[p] + (size_t)(hh*B_ + b)*NT_*KD_;
      #pragma unroll
      for (int i = 0; i < 4; i++){
        int t = r0 + rg*4 + i;
        if (t < NT_){
          float lo, hi; unpack2(acc[i], lo, hi);
          dst[(size_t)t*KD_ + kk] = lo + hi;
        }
      }
    }
  }
}

// ====================== Kernel 2: station projections ======================
__global__ __launch_bounds__(352) void k_proj_st(
    const float* __restrict__ q, const float* __restrict__ h,
    const float* __restrict__ Wqst, const float* __restrict__ Wks,
    const float* __restrict__ Wvs)
{
  __shared__ float sxq[NS_*D_], sxh[NS_*D_], sw[D_*KD_];
  int b = blockIdx.x, tid = threadIdx.x;
  for (int idx = tid; idx < NS_*D_/4; idx += blockDim.x){
    int row = idx >> 5, d4 = idx & 31;
    size_t goff = ((size_t)(b*NN_ + row))*D_ + d4*4;
    ((float4*)sxq)[idx] = *(const float4*)(q + goff);
    ((float4*)sxh)[idx] = *(const float4*)(h + goff);
  }
  const float* Wp[3] = {Wqst, Wks, Wvs};
  for (int p = 0; p < 3; p++){
    const float* src = (p == 0) ? sxq : sxh;
    float scale = (p == 0) ? QSCALE : 1.0f;
    float* Dst = (p == 0) ? g_Qst : (p == 1 ? g_Ks : g_Vs);
    for (int hh = 0; hh < NH_; hh++){
      __syncthreads();
      const float* wp = Wp[p] + hh*D_*KD_;
      for (int idx = tid; idx < D_*KD_; idx += blockDim.x) sw[idx] = wp[idx]*scale;
      __syncthreads();
      if (tid < NS_*KD_){
        int s = tid >> 4, k = tid & 15;
        float a = 0.f;
        #pragma unroll 8
        for (int d = 0; d < D_; d++) a += src[s*D_ + d] * sw[d*KD_ + k];
        Dst[((size_t)(hh*B_ + b)*NS_ + s)*KD_ + k] = a;
      }
    }
  }
}

// ================ Kernel 3: token-query attention (dominant) ===============
// Block = (q-tile of 256, b, h). Thread = one query. K/V chunks of 64 keys
// double-buffered via cp.async; all smem reads are warp broadcasts.
// Softmax without max (scores bounded ~16 << exp2 overflow), NORM*log2e
// pre-folded into Q. heads_t = A_tt@V_c / l_tt + A_ts@V_s / l_ts.
__global__ __launch_bounds__(256) void k_attn_tok()
{
  __shared__ ull sK[2][64*8];
  __shared__ ull sV[2][64*8];
  int hh = blockIdx.z, b = blockIdx.y;
  int tid = threadIdx.x;
  int t = blockIdx.x * 256 + tid;
  bool valid = t < NT_;
  int tc = valid ? t : 0;
  size_t hb = (size_t)(hh*B_ + b);
  const float* Kg = g_Kc + hb*NT_*KD_;
  const float* Vg = g_Vc + hb*NT_*KD_;

  ull q2[8];
  { const ulonglong2* qp = (const ulonglong2*)(g_Qtt + (hb*NT_ + tc)*KD_);
    ulonglong2 a0 = qp[0], a1 = qp[1], a2 = qp[2], a3 = qp[3];
    q2[0]=a0.x; q2[1]=a0.y; q2[2]=a1.x; q2[3]=a1.y;
    q2[4]=a2.x; q2[5]=a2.y; q2[6]=a3.x; q2[7]=a3.y; }

  ull acc[8] = {0,0,0,0,0,0,0,0};
  float l = 0.f;

  int row = tid >> 2, d4 = tid & 3;           // 256 threads -> 64 rows x 4 f4
  { // preload chunk 0
    if (row < NT_){
      cp_async16(&sK[0][row*8 + d4*2], Kg + (size_t)row*KD_ + d4*4);
      cp_async16(&sV[0][row*8 + d4*2], Vg + (size_t)row*KD_ + d4*4);
    }
    cp_commit();
  }
  const int nch = (NT_ + 63)/64;              // 16
  for (int c = 0; c < nch; c++){
    if (c + 1 < nch){
      int gr = (c+1)*64 + row;
      int nb = (c+1)&1;
      if (gr < NT_){
        cp_async16(&sK[nb][row*8 + d4*2], Kg + (size_t)gr*KD_ + d4*4);
        cp_async16(&sV[nb][row*8 + d4*2], Vg + (size_t)gr*KD_ + d4*4);
      }
      cp_commit();
      cp_wait<1>();
    } else {
      cp_wait<0>();
    }
    __syncthreads();
    int cn = min(64, NT_ - c*64);
    const ull* Ks = sK[c&1];
    const ull* Vs = sV[c&1];
    if (valid){
      #pragma unroll 2
      for (int j = 0; j < cn; j++){
        const ulonglong2* kp = (const ulonglong2*)(Ks + j*8);
        ulonglong2 k0 = kp[0], k1 = kp[1], k2 = kp[2], k3 = kp[3];
        ull sa = fmul2(q2[0], k0.x);
        ull sb = fmul2(q2[1], k0.y);
        sa = ffma2(q2[2], k1.x, sa);
        sb = ffma2(q2[3], k1.y, sb);
        sa = ffma2(q2[4], k2.x, sa);
        sb = ffma2(q2[5], k2.y, sb);
        sa = ffma2(q2[6], k3.x, sa);
        sb = ffma2(q2[7], k3.y, sb);
        float lo, hi; unpack2(fadd2(sa, sb), lo, hi);
        float p = ex2f(lo + hi);
        l += p;
        ull p2 = pack2(p, p);
        const ulonglong2* vp = (const ulonglong2*)(Vs + j*8);
        ulonglong2 v0 = vp[0], v1 = vp[1], v2 = vp[2], v3 = vp[3];
        acc[0] = ffma2(p2, v0.x, acc[0]);
        acc[1] = ffma2(p2, v0.y, acc[1]);
        acc[2] = ffma2(p2, v1.x, acc[2]);
        acc[3] = ffma2(p2, v1.y, acc[3]);
        acc[4] = ffma2(p2, v2.x, acc[4]);
        acc[5] = ffma2(p2, v2.y, acc[5]);
        acc[6] = ffma2(p2, v3.x, acc[6]);
        acc[7] = ffma2(p2, v3.y, acc[7]);
      }
    }
    __syncthreads();
  }
  { // normalize token-attention part
    float inv = 1.0f / l;
    ull inv2 = pack2(inv, inv);
    #pragma unroll
    for (int i = 0; i < 8; i++) acc[i] = fmul2(acc[i], inv2);
  }
  // ---- station keys (separate softmax, 21 keys) ----
  const float* Ksg = g_Ks + hb*NS_*KD_;
  const float* Vsg = g_Vs + hb*NS_*KD_;
  if (tid < NS_*4){
    cp_async16(&sK[0][row*8 + d4*2], Ksg + row*KD_ + d4*4);
    cp_async16(&sV[0][row*8 + d4*2], Vsg + row*KD_ + d4*4);
  }
  cp_commit(); cp_wait<0>();
  __syncthreads();
  ull qs2[8];
  { const ulonglong2* qp = (const ulonglong2*)(g_Qts + (hb*NT_ + tc)*KD_);
    ulonglong2 a0 = qp[0], a1 = qp[1], a2 = qp[2], a3 = qp[3];
    qs2[0]=a0.x; qs2[1]=a0.y; qs2[2]=a1.x; qs2[3]=a1.y;
    qs2[4]=a2.x; qs2[5]=a2.y; qs2[6]=a3.x; qs2[7]=a3.y; }
  ull accs[8] = {0,0,0,0,0,0,0,0};
  float ls = 0.f;
  if (valid){
    #pragma unroll
    for (int j = 0; j < NS_; j++){
      const ulonglong2* kp = (const ulonglong2*)(sK[0] + j*8);
      ulonglong2 k0 = kp[0], k1 = kp[1], k2 = kp[2], k3 = kp[3];
      ull sa = fmul2(qs2[0], k0.x);
      ull sb = fmul2(qs2[1], k0.y);
      sa = ffma2(qs2[2], k1.x, sa);
      sb = ffma2(qs2[3], k1.y, sb);
      sa = ffma2(qs2[4], k2.x, sa);
      sb = ffma2(qs2[5], k2.y, sb);
      sa = ffma2(qs2[6], k3.x, sa);
      sb = ffma2(qs2[7], k3.y, sb);
      float lo, hi; unpack2(fadd2(sa, sb), lo, hi);
      float p = ex2f(lo + hi);
      ls += p;
      ull p2 = pack2(p, p);
      const ulonglong2* vp = (const ulonglong2*)(sV[0] + j*8);
      ulonglong2 v0 = vp[0], v1 = vp[1], v2 = vp[2], v3 = vp[3];
      accs[0] = ffma2(p2, v0.x, accs[0]);
      accs[1] = ffma2(p2, v0.y, accs[1]);
      accs[2] = ffma2(p2, v1.x, accs[2]);
      accs[3] = ffma2(p2, v1.y, accs[3]);
      accs[4] = ffma2(p2, v2.x, accs[4]);
      accs[5] = ffma2(p2, v2.y, accs[5]);
      accs[6] = ffma2(p2, v3.x, accs[6]);
      accs[7] = ffma2(p2, v3.y, accs[7]);
    }
  }
  if (valid){
    float invs = 1.0f / ls;
    ull invs2 = pack2(invs, invs);
    #pragma unroll
    for (int i = 0; i < 8; i++) acc[i] = ffma2(accs[i], invs2, acc[i]);
    ulonglong2* op = (ulonglong2*)(g_heads + ((size_t)(b*NN_ + NS_ + t)*NH_ + hh)*KD_);
    op[0] = make_ulonglong2(acc[0], acc[1]);
    op[1] = make_ulonglong2(acc[2], acc[3]);
    op[2] = make_ulonglong2(acc[4], acc[5]);
    op[3] = make_ulonglong2(acc[6], acc[7]);
  }
}

// ================ Kernel 4: station-query attention ========================
// Block = (b, h), 21 warps, warp = one station query; lanes split keys.
// Padded smem stride (17) keeps lane-distinct rows conflict-free.
__global__ __launch_bounds__(672) void k_attn_st()
{
  __shared__ float sk4[64][17], sv4[64][17];
  int b = blockIdx.x, hh = blockIdx.y;
  int tid = threadIdx.x;
  int w = tid >> 5, lane = tid & 31;
  size_t hb = (size_t)(hh*B_ + b);
  const float* Kg = g_Kc + hb*NT_*KD_;
  const float* Vg = g_Vc + hb*NT_*KD_;

  float qv[16];
  { const float4* qp = (const float4*)(g_Qst + (hb*NS_ + w)*KD_);
    float4 a0=qp[0], a1=qp[1], a2=qp[2], a3=qp[3];
    qv[0]=a0.x; qv[1]=a0.y; qv[2]=a0.z; qv[3]=a0.w;
    qv[4]=a1.x; qv[5]=a1.y; qv[6]=a1.z; qv[7]=a1.w;
    qv[8]=a2.x; qv[9]=a2.y; qv[10]=a2.z; qv[11]=a2.w;
    qv[12]=a3.x; qv[13]=a3.y; qv[14]=a3.z; qv[15]=a3.w; }

  float acc[16];
  #pragma unroll
  for (int d = 0; d < 16; d++) acc[d] = 0.f;
  float lacc = 0.f;

  const int nch = (NT_ + 63)/64;
  for (int c = 0; c < nch; c++){
    int cn = min(64, NT_ - c*64);
    for (int idx = tid; idx < 64*16; idx += 672){
      int row = idx >> 4, d = idx & 15;
      int gr = c*64 + row;
      float kv = 0.f, vv = 0.f;
      if (gr < NT_){ kv = Kg[(size_t)gr*KD_ + d]; vv = Vg[(size_t)gr*KD_ + d]; }
      sk4[row][d] = kv; sv4[row][d] = vv;
    }
    __syncthreads();
    for (int j = lane; j < cn; j += 32){
      float s = 0.f;
      #pragma unroll
      for (int d = 0; d < 16; d++) s += sk4[j][d] * qv[d];
      float p = ex2f(s);
      lacc += p;
      #pragma unroll
      for (int d = 0; d < 16; d++) acc[d] += p * sv4[j][d];
    }
    __syncthreads();
  }
  #pragma unroll
  for (int off = 16; off > 0; off >>= 1){
    lacc += __shfl_down_sync(0xffffffffu, lacc, off);
    #pragma unroll
    for (int d = 0; d < 16; d++)
      acc[d] += __shfl_down_sync(0xffffffffu, acc[d], off);
  }
  if (lane == 0){
    float inv = 1.0f / lacc;
    float* op = g_heads + ((size_t)(b*NN_ + w)*NH_ + hh)*KD_;
    #pragma unroll
    for (int d = 0; d < 16; d++) op[d] = acc[d]*inv;
  }
}

// ================ Kernel 5: output GEMM ====================================
// out[b,n,:] = heads_flat[b,n,:128] @ Wout_flat[128,128]
__global__ __launch_bounds__(256, 2) void k_out(
    const float* __restrict__ Wout, float* __restrict__ out)
{
  extern __shared__ float sm[];
  float* sA  = sm;              // 64*128
  float* sWt = sm + 64*D_;      // 128*132 transposed
  int m0 = blockIdx.x * 64;
  int tid = threadIdx.x;
  for (int idx = tid; idx < 64*32; idx += 256){
    int r = idx >> 5, d4 = idx & 31;
    ((float4*)(sA + r*D_))[d4] = ((const float4*)(g_heads + (size_t)(m0 + r)*D_))[d4];
  }
  for (int idx = tid; idx < D_*D_; idx += 256){
    int c = idx >> 7, e = idx & 127;
    sWt[e*132 + c] = Wout[idx];
  }
  __syncthreads();
  int rg = tid >> 4, cg = tid & 15;
  ull acc2[4][8];
  #pragma unroll
  for (int i = 0; i < 4; i++)
    #pragma unroll
    for (int e = 0; e < 8; e++) acc2[i][e] = 0ull;
  #pragma unroll 2
  for (int d4 = 0; d4 < 32; d4++){
    ulonglong2 a[4];
    #pragma unroll
    for (int i = 0; i < 4; i++)
      a[i] = *(const ulonglong2*)(sA + (rg*4 + i)*D_ + d4*4);
    #pragma unroll
    for (int e = 0; e < 8; e++){
      ulonglong2 wv = *(const ulonglong2*)(sWt + (cg*8 + e)*132 + d4*4);
      #pragma unroll
      for (int i = 0; i < 4; i++){
        acc2[i][e] = ffma2(a[i].x, wv.x, acc2[i][e]);
        acc2[i][e] = ffma2(a[i].y, wv.y, acc2[i][e]);
      }
    }
  }
  #pragma unroll
  for (int i = 0; i < 4; i++){
    #pragma unroll
    for (int e = 0; e < 8; e++){
      float lo, hi; unpack2(acc2[i][e], lo, hi);
      out[(size_t)(m0 + rg*4 + i)*D_ + cg*8 + e] = lo + hi;
    }
  }
}

// ===========================================================================
extern "C" void kernel_launch(void* const* d_in, const int* in_sizes, int n_in,
                              void* d_out, int out_size)
{
  const float* q     = (const float*)d_in[0];
  const float* h     = (const float*)d_in[1];
  const float* Wq_ts = (const float*)d_in[2];   // W_query_custom    -> Q_ts
  const float* Wq_tt = (const float*)d_in[3];   // W_query_custom_1  -> Q_tt
  const float* Wk_c  = (const float*)d_in[4];   // W_key_custom
  const float* Wv_c  = (const float*)d_in[5];   // W_val_custom
  const float* Wq_st = (const float*)d_in[6];   // W_query_charge_1  -> Q_st
  const float* Wk_s  = (const float*)d_in[7];   // W_key_charge
  const float* Wv_s  = (const float*)d_in[8];   // W_val_charge
  const float* Wout  = (const float*)d_in[9];
  float* out = (float*)d_out;

  int smem1 = (2*64*D_ + 16*132)*(int)sizeof(float);
  cudaFuncSetAttribute(k_proj_tok, cudaFuncAttributeMaxDynamicSharedMemorySize, smem1);
  int smem5 = (64*D_ + D_*132)*(int)sizeof(float);
  cudaFuncSetAttribute(k_out, cudaFuncAttributeMaxDynamicSharedMemorySize, smem5);

  k_proj_tok<<<dim3(16, 32), 256, smem1>>>(q, h, Wq_tt, Wq_ts, Wk_c, Wv_c);
  k_proj_st<<<32, 352>>>(q, h, Wq_st, Wk_s, Wv_s);
  k_attn_tok<<<dim3(4, 32, 8), 256>>>();
  k_attn_st<<<dim3(32, 8), 672>>>();
  k_out<<<512, 256, smem5>>>(Wout, out);
}

// round 6
// speedup vs baseline: 1.5009x; 1.5009x over previous
#include <cuda_runtime.h>
#include <cstdint>

typedef unsigned long long ull;

#define B_   32
#define NH_  8
#define NN_  1024
#define NS_  21
#define NT_  1003
#define D_   128
#define KD_  16
#define HB_  (NH_*B_)

// NORM * log2(e) folded into query projections so softmax uses raw ex2.
#define QSCALE 0.36067376022224085f

#define CHUNK 128
#define KSTR  20    // K smem row stride (floats): conflict-free score-frag loads, 16B rows
#define VSTR  24    // V smem row stride (floats): conflict-free PV-frag loads, 16B rows

// ---------------- scratch (device globals; no allocation allowed) ----------
__device__ float g_Qtt[HB_*NT_*KD_];
__device__ float g_Qts[HB_*NT_*KD_];
__device__ float g_Kc [HB_*NT_*KD_];
__device__ float g_Vc [HB_*NT_*KD_];
__device__ float g_Qst[HB_*NS_*KD_];
__device__ float g_Ks [HB_*NS_*KD_];
__device__ float g_Vs [HB_*NS_*KD_];
__device__ float g_heads[B_*NN_*NH_*KD_];   // layout [b][n][h][k]

// ---------------- helpers ---------------------------------------------------
__device__ __forceinline__ ull pack2(float lo, float hi){
  ull r; asm("mov.b64 %0, {%1,%2};" : "=l"(r) : "f"(lo), "f"(hi)); return r;
}
__device__ __forceinline__ void unpack2(ull v, float& lo, float& hi){
  asm("mov.b64 {%0,%1}, %2;" : "=f"(lo), "=f"(hi) : "l"(v));
}
__device__ __forceinline__ ull ffma2(ull a, ull b, ull c){
  ull d; asm("fma.rn.f32x2 %0, %1, %2, %3;" : "=l"(d) : "l"(a), "l"(b), "l"(c)); return d;
}
__device__ __forceinline__ float ex2f(float x){
  float r; asm("ex2.approx.f32 %0, %1;" : "=f"(r) : "f"(x)); return r;
}
__device__ __forceinline__ uint32_t tf32r(float f){
  uint32_t u; asm("cvt.rna.tf32.f32 %0, %1;" : "=r"(u) : "f"(f)); return u;
}
__device__ __forceinline__ float tf32rf(float f){ return __uint_as_float(tf32r(f)); }

__device__ __forceinline__ void cp_async16(void* s, const void* g){
  unsigned sa = (unsigned)__cvta_generic_to_shared(s);
  asm volatile("cp.async.cg.shared.global [%0], [%1], 16;" :: "r"(sa), "l"(g));
}
__device__ __forceinline__ void cp_commit(){ asm volatile("cp.async.commit_group;"); }
template<int N> __device__ __forceinline__ void cp_wait(){
  asm volatile("cp.async.wait_group %0;" :: "n"(N) : "memory");
}

// tf32 MMA: D(16x8) += A(16x8,row) * B(8x8,col)
__device__ __forceinline__ void mma8(float& d0, float& d1, float& d2, float& d3,
    uint32_t a0, uint32_t a1, uint32_t a2, uint32_t a3, uint32_t b0, uint32_t b1)
{
  asm("mma.sync.aligned.m16n8k8.row.col.f32.tf32.tf32.f32 "
      "{%0,%1,%2,%3},{%4,%5,%6,%7},{%8,%9},{%0,%1,%2,%3};"
      : "+f"(d0), "+f"(d1), "+f"(d2), "+f"(d3)
      : "r"(a0), "r"(a1), "r"(a2), "r"(a3), "r"(b0), "r"(b1));
}

// Load Q A-fragments for 2 k-steps (head_dim 16). rA,rB pre-clamped row indices.
__device__ __forceinline__ void loadQ(const float* Qb, int rA, int rB, int tig,
                                      uint32_t a[2][4])
{
  #pragma unroll
  for (int ks = 0; ks < 2; ks++){
    a[ks][0] = __float_as_uint(Qb[(size_t)rA*KD_ + tig     + 8*ks]);
    a[ks][1] = __float_as_uint(Qb[(size_t)rB*KD_ + tig     + 8*ks]);
    a[ks][2] = __float_as_uint(Qb[(size_t)rA*KD_ + tig + 4 + 8*ks]);
    a[ks][3] = __float_as_uint(Qb[(size_t)rB*KD_ + tig + 4 + 8*ks]);
  }
}

// One 8-key step: scores (2 MMA) -> exp -> (mask) -> P-frag shuffle -> P@V (2 MMA).
// Accumulates un-normalized output o[2][4] and exp-sums la (rows g), lb (rows g+8).
template<int MASK>
__device__ __forceinline__ void attn_step(
    const float* __restrict__ Ks, const float* __restrict__ Vs,
    const uint32_t (&aQ)[2][4], float (&o)[2][4], float& la, float& lb,
    int n8, int g, int tig, int lane, int nvalid)
{
  float c0 = 0.f, c1 = 0.f, c2 = 0.f, c3 = 0.f;
  const float* kp = Ks + (n8 + g)*KSTR + tig;
  {
    uint32_t b0 = __float_as_uint(kp[0]),  b1 = __float_as_uint(kp[4]);
    mma8(c0,c1,c2,c3, aQ[0][0],aQ[0][1],aQ[0][2],aQ[0][3], b0, b1);
    uint32_t b2 = __float_as_uint(kp[8]),  b3 = __float_as_uint(kp[12]);
    mma8(c0,c1,c2,c3, aQ[1][0],aQ[1][1],aQ[1][2],aQ[1][3], b2, b3);
  }
  float p0 = ex2f(c0), p1 = ex2f(c1), p2 = ex2f(c2), p3 = ex2f(c3);
  if (MASK){
    int col = n8 + tig*2;
    if (col     >= nvalid){ p0 = 0.f; p2 = 0.f; }
    if (col + 1 >= nvalid){ p1 = 0.f; p3 = 0.f; }
  }
  uint32_t u0 = tf32r(p0), u1 = tf32r(p1), u2 = tf32r(p2), u3 = tf32r(p3);
  la += __uint_as_float(u0) + __uint_as_float(u1);
  lb += __uint_as_float(u2) + __uint_as_float(u3);
  // Rearrange D-frag (cols 2t,2t+1) into A-frag (cols t, t+4).
  int src  = (lane & 28) | (tig >> 1);
  int src2 = src + 2;
  uint32_t ev0 = __shfl_sync(0xffffffffu, u0, src ), od0 = __shfl_sync(0xffffffffu, u1, src );
  uint32_t ev1 = __shfl_sync(0xffffffffu, u2, src ), od1 = __shfl_sync(0xffffffffu, u3, src );
  uint32_t ev2 = __shfl_sync(0xffffffffu, u0, src2), od2 = __shfl_sync(0xffffffffu, u1, src2);
  uint32_t ev3 = __shfl_sync(0xffffffffu, u2, src2), od3 = __shfl_sync(0xffffffffu, u3, src2);
  bool odd = (tig & 1);
  uint32_t pa0 = odd ? od0 : ev0;
  uint32_t pa1 = odd ? od1 : ev1;
  uint32_t pa2 = odd ? od2 : ev2;
  uint32_t pa3 = odd ? od3 : ev3;
  #pragma unroll
  for (int nt = 0; nt < 2; nt++){
    uint32_t vb0 = __float_as_uint(Vs[(n8 + tig    )*VSTR + nt*8 + g]);
    uint32_t vb1 = __float_as_uint(Vs[(n8 + tig + 4)*VSTR + nt*8 + g]);
    mma8(o[nt][0], o[nt][1], o[nt][2], o[nt][3], pa0, pa1, pa2, pa3, vb0, vb1);
  }
}

// Cooperative chunk staging: 128 keys x 16 floats of K and V (256 threads, 4 cp each).
__device__ __forceinline__ void stage_chunk(float* sKb, float* sVb,
    const float* __restrict__ Kg, const float* __restrict__ Vg, int kbase, int tid)
{
  #pragma unroll
  for (int i = 0; i < 2; i++){
    int f4  = tid + i*256;
    int row = f4 >> 2, qq = f4 & 3;
    int gr  = kbase + row;
    if (gr < NT_){
      cp_async16(sKb + row*KSTR + qq*4, Kg + (size_t)gr*KD_ + qq*4);
      cp_async16(sVb + row*VSTR + qq*4, Vg + (size_t)gr*KD_ + qq*4);
    }
  }
}

// ====================== Kernel 1: token projections ========================
__global__ __launch_bounds__(256) void k_proj_tok(
    const float* __restrict__ q, const float* __restrict__ h,
    const float* __restrict__ Wqtt, const float* __restrict__ Wqts,
    const float* __restrict__ Wk, const float* __restrict__ Wv)
{
  extern __shared__ float sm[];
  float* sxq = sm;                  // 64*128
  float* sxh = sm + 64*D_;          // 64*128
  float* swt = sm + 2*64*D_;        // 16*132 (transposed weight, padded)

  int b  = blockIdx.y;
  int r0 = blockIdx.x * 64;
  int tid = threadIdx.x;

  #pragma unroll
  for (int i = 0; i < 8; i++){
    int idx = tid + i*256;
    int row = idx >> 5, d4 = idx & 31;
    int t = r0 + row; if (t > NT_-1) t = NT_-1;
    size_t goff = ((size_t)(b*NN_ + NS_ + t))*D_ + d4*4;
    ((float4*)(sxq + row*D_))[d4] = *(const float4*)(q + goff);
    ((float4*)(sxh + row*D_))[d4] = *(const float4*)(h + goff);
  }

  const float* Wp[4] = {Wqtt, Wqts, Wk, Wv};
  float* Dp[4]; Dp[0]=g_Qtt; Dp[1]=g_Qts; Dp[2]=g_Kc; Dp[3]=g_Vc;

  int rg = tid >> 4, kk = tid & 15;
  for (int p = 0; p < 4; p++){
    const float* src = (p < 2) ? sxq : sxh;
    float scale = (p < 2) ? QSCALE : 1.0f;
    for (int hh = 0; hh < NH_; hh++){
      __syncthreads();
      const float* wp = Wp[p] + hh*D_*KD_;
      #pragma unroll
      for (int i = 0; i < 8; i++){
        int idx = tid + i*256;
        int d = idx >> 4, k2 = idx & 15;
        swt[k2*132 + d] = wp[idx] * scale;
      }
      __syncthreads();
      ull acc[4] = {0,0,0,0};
      #pragma unroll 4
      for (int d4 = 0; d4 < 32; d4++){
        ulonglong2 w = *(const ulonglong2*)(swt + kk*132 + d4*4);
        #pragma unroll
        for (int i = 0; i < 4; i++){
          ulonglong2 x = *(const ulonglong2*)(src + (rg*4 + i)*D_ + d4*4);
          acc[i] = ffma2(x.x, w.x, acc[i]);
          acc[i] = ffma2(x.y, w.y, acc[i]);
        }
      }
      float* dst = Dp[p] + (size_t)(hh*B_ + b)*NT_*KD_;
      #pragma unroll
      for (int i = 0; i < 4; i++){
        int t = r0 + rg*4 + i;
        if (t < NT_){
          float lo, hi; unpack2(acc[i], lo, hi);
          dst[(size_t)t*KD_ + kk] = tf32rf(lo + hi);   // tf32-ready for MMA
        }
      }
    }
  }
}

// ====================== Kernel 2: station projections ======================
__global__ __launch_bounds__(352) void k_proj_st(
    const float* __restrict__ q, const float* __restrict__ h,
    const float* __restrict__ Wqst, const float* __restrict__ Wks,
    const float* __restrict__ Wvs)
{
  __shared__ float sxq[NS_*D_], sxh[NS_*D_], sw[D_*KD_];
  int b = blockIdx.x, tid = threadIdx.x;
  for (int idx = tid; idx < NS_*D_/4; idx += blockDim.x){
    int row = idx >> 5, d4 = idx & 31;
    size_t goff = ((size_t)(b*NN_ + row))*D_ + d4*4;
    ((float4*)sxq)[idx] = *(const float4*)(q + goff);
    ((float4*)sxh)[idx] = *(const float4*)(h + goff);
  }
  const float* Wp[3] = {Wqst, Wks, Wvs};
  for (int p = 0; p < 3; p++){
    const float* src = (p == 0) ? sxq : sxh;
    float scale = (p == 0) ? QSCALE : 1.0f;
    float* Dst = (p == 0) ? g_Qst : (p == 1 ? g_Ks : g_Vs);
    for (int hh = 0; hh < NH_; hh++){
      __syncthreads();
      const float* wp = Wp[p] + hh*D_*KD_;
      for (int idx = tid; idx < D_*KD_; idx += blockDim.x) sw[idx] = wp[idx]*scale;
      __syncthreads();
      if (tid < NS_*KD_){
        int s = tid >> 4, k = tid & 15;
        float a = 0.f;
        #pragma unroll 8
        for (int d = 0; d < D_; d++) a += src[s*D_ + d] * sw[d*KD_ + k];
        Dst[((size_t)(hh*B_ + b)*NS_ + s)*KD_ + k] = tf32rf(a);
      }
    }
  }
}

// ================ Kernel 3: token-query attention (tf32 MMA) ===============
// Block = (128-query tile, b, h), 8 warps; warp = 16 queries x all keys.
// Two softmaxes (token keys 1003 + station keys 21), no online max
// (QSCALE folds NORM*log2e; scores bounded, raw ex2 safe); l accumulated
// per-lane, reduced once at the end.
__global__ __launch_bounds__(256) void k_attn_tok()
{
  extern __shared__ float dsm[];
  float* sK0 = dsm;                                   // [2][128*KSTR]
  float* sV0 = dsm + 2*CHUNK*KSTR;                    // [2][128*VSTR]
  float* sKs = dsm + 2*CHUNK*KSTR + 2*CHUNK*VSTR;     // [24*KSTR]
  float* sVs = sKs + 24*KSTR;                         // [24*VSTR]

  int hh = blockIdx.z, b = blockIdx.y;
  int tid = threadIdx.x;
  int w = tid >> 5, lane = tid & 31;
  int g = lane >> 2, tig = lane & 3;
  size_t hb = (size_t)(hh*B_ + b);
  const float* Kg = g_Kc + hb*NT_*KD_;
  const float* Vg = g_Vc + hb*NT_*KD_;

  int qrow = blockIdx.x * 128 + w*16;
  int rA = min(qrow + g,     NT_-1);
  int rB = min(qrow + g + 8, NT_-1);
  uint32_t aT[2][4], aS[2][4];
  loadQ(g_Qtt + hb*NT_*KD_, rA, rB, tig, aT);
  loadQ(g_Qts + hb*NT_*KD_, rA, rB, tig, aS);

  // zero-fill station smem pad rows (21..23) so masked-key V reads stay finite
  for (int i = tid; i < 3*KSTR; i += 256) sKs[21*KSTR + i] = 0.f;
  for (int i = tid; i < 3*VSTR; i += 256) sVs[21*VSTR + i] = 0.f;
  // stage station K/V (21 rows) + chunk 0, one cp group
  if (tid < 96){
    int row = tid >> 2, qq = tid & 3;
    if (row < NS_){
      cp_async16(sKs + row*KSTR + qq*4, g_Ks + (hb*NS_ + row)*KD_ + qq*4);
      cp_async16(sVs + row*VSTR + qq*4, g_Vs + (hb*NS_ + row)*KD_ + qq*4);
    }
  }
  stage_chunk(sK0, sV0 , Kg, Vg, 0, tid);
  cp_commit();

  float ot[2][4] = {{0,0,0,0},{0,0,0,0}};
  float os[2][4] = {{0,0,0,0},{0,0,0,0}};
  float lta = 0.f, ltb = 0.f, lsa = 0.f, lsb = 0.f;

  const int nch = (NT_ + CHUNK - 1)/CHUNK;   // 8
  for (int c = 0; c < nch; c++){
    if (c + 1 < nch){
      int nb = (c+1) & 1;
      stage_chunk(sK0 + nb*CHUNK*KSTR, sV0 + nb*CHUNK*VSTR, Kg, Vg, (c+1)*CHUNK, tid);
      cp_commit();
      cp_wait<1>();
    } else {
      cp_wait<0>();
    }
    __syncthreads();
    if (c == 0){
      attn_step<0>(sKs, sVs, aS, os, lsa, lsb, 0,  g, tig, lane, 0);
      attn_step<0>(sKs, sVs, aS, os, lsa, lsb, 8,  g, tig, lane, 0);
      attn_step<1>(sKs, sVs, aS, os, lsa, lsb, 16, g, tig, lane, NS_);
    }
    const float* Ks = sK0 + (c&1)*CHUNK*KSTR;
    const float* Vs = sV0 + (c&1)*CHUNK*VSTR;
    int nv = min(CHUNK, NT_ - c*CHUNK);
    int nf = nv >> 3;
    #pragma unroll 4
    for (int n = 0; n < nf; n++)
      attn_step<0>(Ks, Vs, aT, ot, lta, ltb, n*8, g, tig, lane, 0);
    if (nv & 7)
      attn_step<1>(Ks, Vs, aT, ot, lta, ltb, nf*8, g, tig, lane, nv);
    __syncthreads();
  }

  // full row sums: butterfly across the 4 lanes of each quad
  lta += __shfl_xor_sync(0xffffffffu, lta, 1); lta += __shfl_xor_sync(0xffffffffu, lta, 2);
  ltb += __shfl_xor_sync(0xffffffffu, ltb, 1); ltb += __shfl_xor_sync(0xffffffffu, ltb, 2);
  lsa += __shfl_xor_sync(0xffffffffu, lsa, 1); lsa += __shfl_xor_sync(0xffffffffu, lsa, 2);
  lsb += __shfl_xor_sync(0xffffffffu, lsb, 1); lsb += __shfl_xor_sync(0xffffffffu, lsb, 2);
  float ita = 1.f/lta, itb = 1.f/ltb, isa = 1.f/lsa, isb = 1.f/lsb;

  int row0 = qrow + g, row1 = qrow + g + 8;
  #pragma unroll
  for (int nt = 0; nt < 2; nt++){
    if (row0 < NT_){
      float2 v; v.x = ot[nt][0]*ita + os[nt][0]*isa;
                v.y = ot[nt][1]*ita + os[nt][1]*isa;
      *(float2*)(g_heads + ((size_t)(b*NN_ + NS_ + row0)*NH_ + hh)*KD_ + nt*8 + 2*tig) = v;
    }
    if (row1 < NT_){
      float2 v; v.x = ot[nt][2]*itb + os[nt][2]*isb;
                v.y = ot[nt][3]*itb + os[nt][3]*isb;
      *(float2*)(g_heads + ((size_t)(b*NN_ + NS_ + row1)*NH_ + hh)*KD_ + nt*8 + 2*tig) = v;
    }
  }
}

// ================ Kernel 4: station-query attention (tf32 MMA) =============
// Block per (h,b); 8 warps = 2 query row-tiles x 4 key stripes; partial
// exp-sums/outputs add linearly (no max), reduced through smem.
__global__ __launch_bounds__(256) void k_attn_st()
{
  extern __shared__ float dsm[];
  float* sK0 = dsm;                                 // [2][128*KSTR]
  float* sV0 = dsm + 2*CHUNK*KSTR;                  // [2][128*VSTR]
  float* red = dsm + 2*CHUNK*KSTR + 2*CHUNK*VSTR;   // [8][32][10]

  int hh = blockIdx.x >> 5, b = blockIdx.x & 31;
  int tid = threadIdx.x;
  int w = tid >> 5, lane = tid & 31;
  int g = lane >> 2, tig = lane & 3;
  int rt = w & 1, s = w >> 1;
  size_t hb = (size_t)(hh*B_ + b);
  const float* Kg = g_Kc + hb*NT_*KD_;
  const float* Vg = g_Vc + hb*NT_*KD_;

  int rA = min(rt*16 + g,     NS_-1);
  int rB = min(rt*16 + g + 8, NS_-1);
  uint32_t aQ[2][4];
  loadQ(g_Qst + hb*NS_*KD_, rA, rB, tig, aQ);

  float o[2][4] = {{0,0,0,0},{0,0,0,0}};
  float la = 0.f, lb = 0.f;

  stage_chunk(sK0, sV0, Kg, Vg, 0, tid);
  cp_commit();
  const int nch = (NT_ + CHUNK - 1)/CHUNK;
  for (int c = 0; c < nch; c++){
    if (c + 1 < nch){
      int nb = (c+1) & 1;
      stage_chunk(sK0 + nb*CHUNK*KSTR, sV0 + nb*CHUNK*VSTR, Kg, Vg, (c+1)*CHUNK, tid);
      cp_commit();
      cp_wait<1>();
    } else {
      cp_wait<0>();
    }
    __syncthreads();
    const float* Ks = sK0 + (c&1)*CHUNK*KSTR;
    const float* Vs = sV0 + (c&1)*CHUNK*VSTR;
    int nv = min(CHUNK, NT_ - c*CHUNK);
    #pragma unroll
    for (int j = 0; j < 4; j++){
      int n8 = (s*4 + j)*8;
      if (n8 + 8 <= nv)
        attn_step<0>(Ks, Vs, aQ, o, la, lb, n8, g, tig, lane, 0);
      else if (n8 < nv)
        attn_step<1>(Ks, Vs, aQ, o, la, lb, n8, g, tig, lane, nv);
    }
    __syncthreads();
  }

  float* rp = red + (w*32 + lane)*10;
  rp[0]=o[0][0]; rp[1]=o[0][1]; rp[2]=o[0][2]; rp[3]=o[0][3];
  rp[4]=o[1][0]; rp[5]=o[1][1]; rp[6]=o[1][2]; rp[7]=o[1][3];
  rp[8]=la; rp[9]=lb;
  __syncthreads();
  if (w < 2){
    #pragma unroll
    for (int ss = 1; ss < 4; ss++){
      float* qp = red + ((w + 2*ss)*32 + lane)*10;
      o[0][0]+=qp[0]; o[0][1]+=qp[1]; o[0][2]+=qp[2]; o[0][3]+=qp[3];
      o[1][0]+=qp[4]; o[1][1]+=qp[5]; o[1][2]+=qp[6]; o[1][3]+=qp[7];
      la += qp[8]; lb += qp[9];
    }
    la += __shfl_xor_sync(0xffffffffu, la, 1); la += __shfl_xor_sync(0xffffffffu, la, 2);
    lb += __shfl_xor_sync(0xffffffffu, lb, 1); lb += __shfl_xor_sync(0xffffffffu, lb, 2);
    float ia = 1.f/la, ib = 1.f/lb;
    int r0 = rt*16 + g, r1 = r0 + 8;
    #pragma unroll
    for (int nt = 0; nt < 2; nt++){
      if (r0 < NS_){
        float2 v; v.x = o[nt][0]*ia; v.y = o[nt][1]*ia;
        *(float2*)(g_heads + ((size_t)(b*NN_ + r0)*NH_ + hh)*KD_ + nt*8 + 2*tig) = v;
      }
      if (r1 < NS_){
        float2 v; v.x = o[nt][2]*ib; v.y = o[nt][3]*ib;
        *(float2*)(g_heads + ((size_t)(b*NN_ + r1)*NH_ + hh)*KD_ + nt*8 + 2*tig) = v;
      }
    }
  }
}

// ================ Kernel 5: output GEMM ====================================
__global__ __launch_bounds__(256, 2) void k_out(
    const float* __restrict__ Wout, float* __restrict__ out)
{
  extern __shared__ float sm[];
  float* sA  = sm;              // 64*128
  float* sWt = sm + 64*D_;      // 128*132 transposed
  int m0 = blockIdx.x * 64;
  int tid = threadIdx.x;
  for (int idx = tid; idx < 64*32; idx += 256){
    int r = idx >> 5, d4 = idx & 31;
    ((float4*)(sA + r*D_))[d4] = ((const float4*)(g_heads + (size_t)(m0 + r)*D_))[d4];
  }
  for (int idx = tid; idx < D_*D_; idx += 256){
    int c = idx >> 7, e = idx & 127;
    sWt[e*132 + c] = Wout[idx];
  }
  __syncthreads();
  int rg = tid >> 4, cg = tid & 15;
  ull acc2[4][8];
  #pragma unroll
  for (int i = 0; i < 4; i++)
    #pragma unroll
    for (int e = 0; e < 8; e++) acc2[i][e] = 0ull;
  #pragma unroll 2
  for (int d4 = 0; d4 < 32; d4++){
    ulonglong2 a[4];
    #pragma unroll
    for (int i = 0; i < 4; i++)
      a[i] = *(const ulonglong2*)(sA + (rg*4 + i)*D_ + d4*4);
    #pragma unroll
    for (int e = 0; e < 8; e++){
      ulonglong2 wv = *(const ulonglong2*)(sWt + (cg*8 + e)*132 + d4*4);
      #pragma unroll
      for (int i = 0; i < 4; i++){
        acc2[i][e] = ffma2(a[i].x, wv.x, acc2[i][e]);
        acc2[i][e] = ffma2(a[i].y, wv.y, acc2[i][e]);
      }
    }
  }
  #pragma unroll
  for (int i = 0; i < 4; i++){
    #pragma unroll
    for (int e = 0; e < 8; e++){
      float lo, hi; unpack2(acc2[i][e], lo, hi);
      out[(size_t)(m0 + rg*4 + i)*D_ + cg*8 + e] = lo + hi;
    }
  }
}

// ===========================================================================
extern "C" void kernel_launch(void* const* d_in, const int* in_sizes, int n_in,
                              void* d_out, int out_size)
{
  const float* q     = (const float*)d_in[0];
  const float* h     = (const float*)d_in[1];
  const float* Wq_ts = (const float*)d_in[2];   // W_query_custom    -> Q_ts
  const float* Wq_tt = (const float*)d_in[3];   // W_query_custom_1  -> Q_tt
  const float* Wk_c  = (const float*)d_in[4];   // W_key_custom
  const float* Wv_c  = (const float*)d_in[5];   // W_val_custom
  const float* Wq_st = (const float*)d_in[6];   // W_query_charge_1  -> Q_st
  const float* Wk_s  = (const float*)d_in[7];   // W_key_charge
  const float* Wv_s  = (const float*)d_in[8];   // W_val_charge
  const float* Wout  = (const float*)d_in[9];
  float* out = (float*)d_out;

  int smem1 = (2*64*D_ + 16*132)*(int)sizeof(float);
  cudaFuncSetAttribute(k_proj_tok, cudaFuncAttributeMaxDynamicSharedMemorySize, smem1);
  int smem5 = (64*D_ + D_*132)*(int)sizeof(float);
  cudaFuncSetAttribute(k_out, cudaFuncAttributeMaxDynamicSharedMemorySize, smem5);
  int smem3 = (2*CHUNK*KSTR + 2*CHUNK*VSTR + 24*KSTR + 24*VSTR)*(int)sizeof(float);
  cudaFuncSetAttribute(k_attn_tok, cudaFuncAttributeMaxDynamicSharedMemorySize, smem3);
  int smem4 = (2*CHUNK*KSTR + 2*CHUNK*VSTR + 8*32*10)*(int)sizeof(float);
  cudaFuncSetAttribute(k_attn_st, cudaFuncAttributeMaxDynamicSharedMemorySize, smem4);

  k_proj_tok<<<dim3(16, 32), 256, smem1>>>(q, h, Wq_tt, Wq_ts, Wk_c, Wv_c);
  k_proj_st<<<32, 352>>>(q, h, Wq_st, Wk_s, Wv_s);
  k_attn_tok<<<dim3(8, 32, 8), 256, smem3>>>();
  k_attn_st<<<256, 256, smem4>>>();
  k_out<<<512, 256, smem5>>>(Wout, out);
}

// round 8
// speedup vs baseline: 1.5429x; 1.0280x over previous
#include <cuda_runtime.h>
#include <cstdint>

typedef unsigned long long ull;

#define B_   32
#define NH_  8
#define NN_  1024
#define NS_  21
#define NT_  1003
#define D_   128
#define KD_  16
#define HB_  (NH_*B_)

// NORM * log2(e) folded into query projections so softmax uses raw ex2.
#define QSCALE 0.36067376022224085f

#define CHUNK 128
#define KSTR  20    // K smem row stride (floats): conflict-free score-frag loads
#define VSTR  24    // V smem row stride (floats): conflict-free PV-frag loads
#define XSTR  132   // X smem row stride in proj

// ---------------- scratch (device globals; no allocation allowed) ----------
__device__ float g_Qtt[HB_*NT_*KD_];
__device__ float g_Qts[HB_*NT_*KD_];
__device__ float g_Kc [HB_*NT_*KD_];
__device__ float g_Vc [HB_*NT_*KD_];
__device__ float g_Qst[HB_*NS_*KD_];
__device__ float g_Ks [HB_*NS_*KD_];
__device__ float g_Vs [HB_*NS_*KD_];
__device__ float g_heads[B_*NN_*NH_*KD_];   // layout [b][n][h][k]

// ---------------- helpers ---------------------------------------------------
__device__ __forceinline__ void unpack2(ull v, float& lo, float& hi){
  asm("mov.b64 {%0,%1}, %2;" : "=f"(lo), "=f"(hi) : "l"(v));
}
__device__ __forceinline__ ull ffma2(ull a, ull b, ull c){
  ull d; asm("fma.rn.f32x2 %0, %1, %2, %3;" : "=l"(d) : "l"(a), "l"(b), "l"(c)); return d;
}
__device__ __forceinline__ float ex2f(float x){
  float r; asm("ex2.approx.f32 %0, %1;" : "=f"(r) : "f"(x)); return r;
}
__device__ __forceinline__ uint32_t tf32r(float f){
  uint32_t u; asm("cvt.rna.tf32.f32 %0, %1;" : "=r"(u) : "f"(f)); return u;
}
__device__ __forceinline__ float tf32rf(float f){ return __uint_as_float(tf32r(f)); }

__device__ __forceinline__ void cp_async16(void* s, const void* g){
  unsigned sa = (unsigned)__cvta_generic_to_shared(s);
  asm volatile("cp.async.cg.shared.global [%0], [%1], 16;" :: "r"(sa), "l"(g));
}
__device__ __forceinline__ void cp_commit(){ asm volatile("cp.async.commit_group;"); }
template<int N> __device__ __forceinline__ void cp_wait(){
  asm volatile("cp.async.wait_group %0;" :: "n"(N) : "memory");
}

// tf32 MMA: D(16x8) += A(16x8,row) * B(8x8,col)
__device__ __forceinline__ void mma8(float& d0, float& d1, float& d2, float& d3,
    uint32_t a0, uint32_t a1, uint32_t a2, uint32_t a3, uint32_t b0, uint32_t b1)
{
  asm("mma.sync.aligned.m16n8k8.row.col.f32.tf32.tf32.f32 "
      "{%0,%1,%2,%3},{%4,%5,%6,%7},{%8,%9},{%0,%1,%2,%3};"
      : "+f"(d0), "+f"(d1), "+f"(d2), "+f"(d3)
      : "r"(a0), "r"(a1), "r"(a2), "r"(a3), "r"(b0), "r"(b1));
}

// Load Q A-fragments for 2 k-steps (head_dim 16). rA,rB pre-clamped row indices.
__device__ __forceinline__ void loadQ(const float* Qb, int rA, int rB, int tig,
                                      uint32_t a[2][4])
{
  #pragma unroll
  for (int ks = 0; ks < 2; ks++){
    a[ks][0] = __float_as_uint(Qb[(size_t)rA*KD_ + tig     + 8*ks]);
    a[ks][1] = __float_as_uint(Qb[(size_t)rB*KD_ + tig     + 8*ks]);
    a[ks][2] = __float_as_uint(Qb[(size_t)rA*KD_ + tig + 4 + 8*ks]);
    a[ks][3] = __float_as_uint(Qb[(size_t)rB*KD_ + tig + 4 + 8*ks]);
  }
}

// One 8-key step: scores (2 MMA) -> exp -> (mask) -> P-frag shuffle ->
// ones-MMA row-sum (ls[0]=row g sum, ls[2]=row g+8 sum; fully reduced) ->
// P@V (2 MMA).
template<int MASK>
__device__ __forceinline__ void attn_step(
    const float* __restrict__ Ks, const float* __restrict__ Vs,
    const uint32_t (&aQ)[2][4], float (&o)[2][4], float (&ls)[4],
    int n8, int g, int tig, int lane, int nvalid)
{
  float c0 = 0.f, c1 = 0.f, c2 = 0.f, c3 = 0.f;
  const float* kp = Ks + (n8 + g)*KSTR + tig;
  {
    uint32_t b0 = __float_as_uint(kp[0]),  b1 = __float_as_uint(kp[4]);
    mma8(c0,c1,c2,c3, aQ[0][0],aQ[0][1],aQ[0][2],aQ[0][3], b0, b1);
    uint32_t b2 = __float_as_uint(kp[8]),  b3 = __float_as_uint(kp[12]);
    mma8(c0,c1,c2,c3, aQ[1][0],aQ[1][1],aQ[1][2],aQ[1][3], b2, b3);
  }
  float p0 = ex2f(c0), p1 = ex2f(c1), p2 = ex2f(c2), p3 = ex2f(c3);
  if (MASK){
    int col = n8 + tig*2;
    if (col     >= nvalid){ p0 = 0.f; p2 = 0.f; }
    if (col + 1 >= nvalid){ p1 = 0.f; p3 = 0.f; }
  }
  uint32_t u0 = tf32r(p0), u1 = tf32r(p1), u2 = tf32r(p2), u3 = tf32r(p3);
  // Rearrange D-frag (cols 2t,2t+1) into A-frag (cols t, t+4).
  int src  = (lane & 28) | (tig >> 1);
  int src2 = src + 2;
  uint32_t ev0 = __shfl_sync(0xffffffffu, u0, src ), od0 = __shfl_sync(0xffffffffu, u1, src );
  uint32_t ev1 = __shfl_sync(0xffffffffu, u2, src ), od1 = __shfl_sync(0xffffffffu, u3, src );
  uint32_t ev2 = __shfl_sync(0xffffffffu, u0, src2), od2 = __shfl_sync(0xffffffffu, u1, src2);
  uint32_t ev3 = __shfl_sync(0xffffffffu, u2, src2), od3 = __shfl_sync(0xffffffffu, u3, src2);
  bool odd = (tig & 1);
  uint32_t pa0 = odd ? od0 : ev0;
  uint32_t pa1 = odd ? od1 : ev1;
  uint32_t pa2 = odd ? od2 : ev2;
  uint32_t pa3 = odd ? od3 : ev3;
  const uint32_t one = 0x3f800000u;          // 1.0f (tf32-exact)
  mma8(ls[0], ls[1], ls[2], ls[3], pa0, pa1, pa2, pa3, one, one);
  #pragma unroll
  for (int nt = 0; nt < 2; nt++){
    uint32_t vb0 = __float_as_uint(Vs[(n8 + tig    )*VSTR + nt*8 + g]);
    uint32_t vb1 = __float_as_uint(Vs[(n8 + tig + 4)*VSTR + nt*8 + g]);
    mma8(o[nt][0], o[nt][1], o[nt][2], o[nt][3], pa0, pa1, pa2, pa3, vb0, vb1);
  }
}

// Cooperative chunk staging: 128 keys x 16 floats of K and V (256 threads).
__device__ __forceinline__ void stage_chunk(float* sKb, float* sVb,
    const float* __restrict__ Kg, const float* __restrict__ Vg, int kbase, int tid)
{
  #pragma unroll
  for (int i = 0; i < 2; i++){
    int f4  = tid + i*256;
    int row = f4 >> 2, qq = f4 & 3;
    int gr  = kbase + row;
    if (gr < NT_){
      cp_async16(sKb + row*KSTR + qq*4, Kg + (size_t)gr*KD_ + qq*4);
      cp_async16(sVb + row*VSTR + qq*4, Vg + (size_t)gr*KD_ + qq*4);
    }
  }
}

// ====================== Kernel 1: all projections ==========================
// blockIdx.x < 16 : token tile of 64 rows, scalar f32x2 (fp32 accuracy —
//                   tf32 proj measured at 1.27e-3 error contribution, FAILS).
// blockIdx.x == 16: station projections (21 rows, scalar).
__global__ __launch_bounds__(256) void k_proj(
    const float* __restrict__ q, const float* __restrict__ h,
    const float* __restrict__ Wqtt, const float* __restrict__ Wqts,
    const float* __restrict__ Wk, const float* __restrict__ Wv,
    const float* __restrict__ Wqst, const float* __restrict__ Wks,
    const float* __restrict__ Wvs)
{
  extern __shared__ float sm[];
  int b  = blockIdx.y;
  int tid = threadIdx.x;

  if (blockIdx.x == 16){
    // ---------------- station projections (scalar) ----------------
    float* sxq = sm;                 // 21*128
    float* sxh = sm + NS_*D_;
    float* sw  = sm + 2*NS_*D_;      // 128*16
    for (int idx = tid; idx < NS_*D_/4; idx += 256){
      int row = idx >> 5, d4 = idx & 31;
      size_t goff = ((size_t)(b*NN_ + row))*D_ + d4*4;
      ((float4*)sxq)[idx] = *(const float4*)(q + goff);
      ((float4*)sxh)[idx] = *(const float4*)(h + goff);
    }
    const float* Wp[3] = {Wqst, Wks, Wvs};
    for (int p = 0; p < 3; p++){
      const float* src = (p == 0) ? sxq : sxh;
      float scale = (p == 0) ? QSCALE : 1.0f;
      float* Dst = (p == 0) ? g_Qst : (p == 1 ? g_Ks : g_Vs);
      for (int hh = 0; hh < NH_; hh++){
        __syncthreads();
        const float* wp = Wp[p] + hh*D_*KD_;
        for (int idx = tid; idx < D_*KD_; idx += 256) sw[idx] = wp[idx]*scale;
        __syncthreads();
        for (int o = tid; o < NS_*KD_; o += 256){
          int s = o >> 4, k = o & 15;
          float a = 0.f;
          #pragma unroll 8
          for (int d = 0; d < D_; d++) a += src[s*D_ + d] * sw[d*KD_ + k];
          Dst[((size_t)(hh*B_ + b)*NS_ + s)*KD_ + k] = tf32rf(a);
        }
      }
    }
    return;
  }

  // ---------------- token projections (scalar f32x2, fp32 accuracy) -------
  float* sxq = sm;                     // 64*XSTR
  float* sxh = sm + 64*XSTR;           // 64*XSTR
  float* swt = sm + 2*64*XSTR;         // 16*XSTR (transposed weight, padded)

  int r0 = blockIdx.x * 64;
  #pragma unroll
  for (int i = 0; i < 8; i++){
    int idx = tid + i*256;              // float4 index, 2048 total
    int row = idx >> 5, d4 = idx & 31;
    int t = r0 + row; if (t > NT_-1) t = NT_-1;   // clamp (guarded on write)
    size_t goff = ((size_t)(b*NN_ + NS_ + t))*D_ + d4*4;
    ((float4*)(sxq + row*XSTR))[d4] = *(const float4*)(q + goff);
    ((float4*)(sxh + row*XSTR))[d4] = *(const float4*)(h + goff);
  }

  const float* Wp[4] = {Wqtt, Wqts, Wk, Wv};
  float* Dp[4]; Dp[0]=g_Qtt; Dp[1]=g_Qts; Dp[2]=g_Kc; Dp[3]=g_Vc;

  int rg = tid >> 4, kk = tid & 15;
  for (int p = 0; p < 4; p++){
    const float* src = (p < 2) ? sxq : sxh;
    float scale = (p < 2) ? QSCALE : 1.0f;
    for (int hh = 0; hh < NH_; hh++){
      __syncthreads();   // also covers initial x load
      const float* wp = Wp[p] + hh*D_*KD_;
      #pragma unroll
      for (int i = 0; i < 8; i++){
        int idx = tid + i*256;          // 2048 weight elems
        int d = idx >> 4, k2 = idx & 15;
        swt[k2*XSTR + d] = wp[idx] * scale;
      }
      __syncthreads();
      ull acc[4] = {0,0,0,0};
      #pragma unroll 4
      for (int d4 = 0; d4 < 32; d4++){
        ulonglong2 w = *(const ulonglong2*)(swt + kk*XSTR + d4*4);
        #pragma unroll
        for (int i = 0; i < 4; i++){
          ulonglong2 x = *(const ulonglong2*)(src + (rg*4 + i)*XSTR + d4*4);
          acc[i] = ffma2(x.x, w.x, acc[i]);
          acc[i] = ffma2(x.y, w.y, acc[i]);
        }
      }
      float* dst = Dp[p] + (size_t)(hh*B_ + b)*NT_*KD_;
      #pragma unroll
      for (int i = 0; i < 4; i++){
        int t = r0 + rg*4 + i;
        if (t < NT_){
          float lo, hi; unpack2(acc[i], lo, hi);
          dst[(size_t)t*KD_ + kk] = tf32rf(lo + hi);   // tf32-ready for MMA
        }
      }
    }
  }
}

// ====================== Kernel 2: all attention ============================
// blockIdx.x < 8 : token-query path (128-query tile, warp = 16 q x all keys).
// blockIdx.x == 8: station-query path (warp = 16 q-rows x key stripe).
// No online max (QSCALE folds NORM*log2e; scores bounded, raw ex2 safe).
// Row sums fall out of the ones-MMA D-fragments already fully reduced.
__global__ __launch_bounds__(256) void k_attn()
{
  extern __shared__ float dsm[];
  float* sK0 = dsm;                                   // [2][128*KSTR]
  float* sV0 = dsm + 2*CHUNK*KSTR;                    // [2][128*VSTR]
  float* sKs = dsm + 2*CHUNK*KSTR + 2*CHUNK*VSTR;     // token: [24*KSTR]
  float* sVs = sKs + 24*KSTR;                         // token: [24*VSTR]
  float* red = dsm + 2*CHUNK*KSTR + 2*CHUNK*VSTR;     // station: [8*32*10]

  int b = blockIdx.y, hh = blockIdx.z;
  int tid = threadIdx.x;
  int w = tid >> 5, lane = tid & 31;
  int g = lane >> 2, tig = lane & 3;
  size_t hb = (size_t)(hh*B_ + b);
  const float* Kg = g_Kc + hb*NT_*KD_;
  const float* Vg = g_Vc + hb*NT_*KD_;
  const int nch = (NT_ + CHUNK - 1)/CHUNK;   // 8

  if (blockIdx.x < 8){
    // ======== token-query path ========
    int qrow = blockIdx.x * 128 + w*16;
    int rA = min(qrow + g,     NT_-1);
    int rB = min(qrow + g + 8, NT_-1);

    // zero station pad rows (21..23) so pad scores are finite then masked
    for (int i = tid; i < 3*KSTR; i += 256) sKs[21*KSTR + i] = 0.f;
    for (int i = tid; i < 3*VSTR; i += 256) sVs[21*VSTR + i] = 0.f;
    // group 1: station K/V
    if (tid < 96){
      int row = tid >> 2, qq = tid & 3;
      if (row < NS_){
        cp_async16(sKs + row*KSTR + qq*4, g_Ks + (hb*NS_ + row)*KD_ + qq*4);
        cp_async16(sVs + row*VSTR + qq*4, g_Vs + (hb*NS_ + row)*KD_ + qq*4);
      }
    }
    cp_commit();
    // group 2: token chunk 0
    stage_chunk(sK0, sV0, Kg, Vg, 0, tid);
    cp_commit();

    uint32_t aT[2][4];
    loadQ(g_Qtt + hb*NT_*KD_, rA, rB, tig, aT);

    // ---- station prologue: full mini-softmax, normalized into os ----
    float os[2][4] = {{0,0,0,0},{0,0,0,0}};
    {
      uint32_t aS[2][4];
      loadQ(g_Qts + hb*NT_*KD_, rA, rB, tig, aS);
      cp_wait<1>();          // group 1 (station) done
      __syncthreads();
      float lsS[4] = {0,0,0,0};
      attn_step<0>(sKs, sVs, aS, os, lsS, 0,  g, tig, lane, 0);
      attn_step<0>(sKs, sVs, aS, os, lsS, 8,  g, tig, lane, 0);
      attn_step<1>(sKs, sVs, aS, os, lsS, 16, g, tig, lane, NS_);
      float isa = 1.f/lsS[0], isb = 1.f/lsS[2];
      #pragma unroll
      for (int nt = 0; nt < 2; nt++){
        os[nt][0] *= isa; os[nt][1] *= isa;
        os[nt][2] *= isb; os[nt][3] *= isb;
      }
    }

    // ---- token mainloop ----
    float ot[2][4] = {{0,0,0,0},{0,0,0,0}};
    float ls[4] = {0,0,0,0};
    for (int c = 0; c < nch; c++){
      if (c + 1 < nch){
        int nb = (c+1) & 1;
        stage_chunk(sK0 + nb*CHUNK*KSTR, sV0 + nb*CHUNK*VSTR, Kg, Vg, (c+1)*CHUNK, tid);
        cp_commit();
        cp_wait<1>();
      } else {
        cp_wait<0>();
      }
      __syncthreads();
      const float* Ks = sK0 + (c&1)*CHUNK*KSTR;
      const float* Vs = sV0 + (c&1)*CHUNK*VSTR;
      int nv = min(CHUNK, NT_ - c*CHUNK);
      int nf = nv >> 3;
      #pragma unroll 4
      for (int n = 0; n < nf; n++)
        attn_step<0>(Ks, Vs, aT, ot, ls, n*8, g, tig, lane, 0);
      if (nv & 7)
        attn_step<1>(Ks, Vs, aT, ot, ls, nf*8, g, tig, lane, nv);
      __syncthreads();
    }

    float ita = 1.f/ls[0], itb = 1.f/ls[2];   // ones-MMA: already full row sums
    int row0 = qrow + g, row1 = qrow + g + 8;
    #pragma unroll
    for (int nt = 0; nt < 2; nt++){
      if (row0 < NT_){
        float2 v; v.x = ot[nt][0]*ita + os[nt][0];
                  v.y = ot[nt][1]*ita + os[nt][1];
        *(float2*)(g_heads + ((size_t)(b*NN_ + NS_ + row0)*NH_ + hh)*KD_ + nt*8 + 2*tig) = v;
      }
      if (row1 < NT_){
        float2 v; v.x = ot[nt][2]*itb + os[nt][2];
                  v.y = ot[nt][3]*itb + os[nt][3];
        *(float2*)(g_heads + ((size_t)(b*NN_ + NS_ + row1)*NH_ + hh)*KD_ + nt*8 + 2*tig) = v;
      }
    }
  } else {
    // ======== station-query path ========
    int rt = w & 1, s = w >> 1;        // 2 q-row-tiles x 4 key stripes
    int rA = min(rt*16 + g,     NS_-1);
    int rB = min(rt*16 + g + 8, NS_-1);
    uint32_t aQ[2][4];
    loadQ(g_Qst + hb*NS_*KD_, rA, rB, tig, aQ);

    float o[2][4] = {{0,0,0,0},{0,0,0,0}};
    float ls[4] = {0,0,0,0};

    stage_chunk(sK0, sV0, Kg, Vg, 0, tid);
    cp_commit();
    for (int c = 0; c < nch; c++){
      if (c + 1 < nch){
        int nb = (c+1) & 1;
        stage_chunk(sK0 + nb*CHUNK*KSTR, sV0 + nb*CHUNK*VSTR, Kg, Vg, (c+1)*CHUNK, tid);
        cp_commit();
        cp_wait<1>();
      } else {
        cp_wait<0>();
      }
      __syncthreads();
      const float* Ks = sK0 + (c&1)*CHUNK*KSTR;
      const float* Vs = sV0 + (c&1)*CHUNK*VSTR;
      int nv = min(CHUNK, NT_ - c*CHUNK);
      #pragma unroll
      for (int j = 0; j < 4; j++){
        int n8 = (s*4 + j)*8;
        if (n8 + 8 <= nv)
          attn_step<0>(Ks, Vs, aQ, o, ls, n8, g, tig, lane, 0);
        else if (n8 < nv)
          attn_step<1>(Ks, Vs, aQ, o, ls, n8, g, tig, lane, nv);
      }
      __syncthreads();
    }

    float* rp = red + (w*32 + lane)*10;
    rp[0]=o[0][0]; rp[1]=o[0][1]; rp[2]=o[0][2]; rp[3]=o[0][3];
    rp[4]=o[1][0]; rp[5]=o[1][1]; rp[6]=o[1][2]; rp[7]=o[1][3];
    rp[8]=ls[0]; rp[9]=ls[2];
    __syncthreads();
    if (w < 2){
      float la = ls[0], lb = ls[2];
      #pragma unroll
      for (int ss = 1; ss < 4; ss++){
        float* qp = red + ((w + 2*ss)*32 + lane)*10;
        o[0][0]+=qp[0]; o[0][1]+=qp[1]; o[0][2]+=qp[2]; o[0][3]+=qp[3];
        o[1][0]+=qp[4]; o[1][1]+=qp[5]; o[1][2]+=qp[6]; o[1][3]+=qp[7];
        la += qp[8]; lb += qp[9];
      }
      float ia = 1.f/la, ib = 1.f/lb;
      int r0 = rt*16 + g, r1 = r0 + 8;
      #pragma unroll
      for (int nt = 0; nt < 2; nt++){
        if (r0 < NS_){
          float2 v; v.x = o[nt][0]*ia; v.y = o[nt][1]*ia;
          *(float2*)(g_heads + ((size_t)(b*NN_ + r0)*NH_ + hh)*KD_ + nt*8 + 2*tig) = v;
        }
        if (r1 < NS_){
          float2 v; v.x = o[nt][2]*ib; v.y = o[nt][3]*ib;
          *(float2*)(g_heads + ((size_t)(b*NN_ + r1)*NH_ + hh)*KD_ + nt*8 + 2*tig) = v;
        }
      }
    }
  }
}

// ================ Kernel 3: output GEMM (fp32 f32x2, value path) ===========
__global__ __launch_bounds__(256, 2) void k_out(
    const float* __restrict__ Wout, float* __restrict__ out)
{
  extern __shared__ float sm[];
  float* sA  = sm;              // 64*128
  float* sWt = sm + 64*D_;      // 128*132 transposed
  int m0 = blockIdx.x * 64;
  int tid = threadIdx.x;
  for (int idx = tid; idx < 64*32; idx += 256){
    int r = idx >> 5, d4 = idx & 31;
    ((float4*)(sA + r*D_))[d4] = ((const float4*)(g_heads + (size_t)(m0 + r)*D_))[d4];
  }
  for (int idx = tid; idx < D_*D_; idx += 256){
    int c = idx >> 7, e = idx & 127;
    sWt[e*132 + c] = Wout[idx];
  }
  __syncthreads();
  int rg = tid >> 4, cg = tid & 15;
  ull acc2[4][8];
  #pragma unroll
  for (int i = 0; i < 4; i++)
    #pragma unroll
    for (int e = 0; e < 8; e++) acc2[i][e] = 0ull;
  #pragma unroll 2
  for (int d4 = 0; d4 < 32; d4++){
    ulonglong2 a[4];
    #pragma unroll
    for (int i = 0; i < 4; i++)
      a[i] = *(const ulonglong2*)(sA + (rg*4 + i)*D_ + d4*4);
    #pragma unroll
    for (int e = 0; e < 8; e++){
      ulonglong2 wv = *(const ulonglong2*)(sWt + (cg*8 + e)*132 + d4*4);
      #pragma unroll
      for (int i = 0; i < 4; i++){
        acc2[i][e] = ffma2(a[i].x, wv.x, acc2[i][e]);
        acc2[i][e] = ffma2(a[i].y, wv.y, acc2[i][e]);
      }
    }
  }
  #pragma unroll
  for (int i = 0; i < 4; i++){
    #pragma unroll
    for (int e = 0; e < 8; e++){
      float lo, hi; unpack2(acc2[i][e], lo, hi);
      out[(size_t)(m0 + rg*4 + i)*D_ + cg*8 + e] = lo + hi;
    }
  }
}

// ===========================================================================
extern "C" void kernel_launch(void* const* d_in, const int* in_sizes, int n_in,
                              void* d_out, int out_size)
{
  const float* q     = (const float*)d_in[0];
  const float* h     = (const float*)d_in[1];
  const float* Wq_ts = (const float*)d_in[2];   // W_query_custom    -> Q_ts
  const float* Wq_tt = (const float*)d_in[3];   // W_query_custom_1  -> Q_tt
  const float* Wk_c  = (const float*)d_in[4];   // W_key_custom
  const float* Wv_c  = (const float*)d_in[5];   // W_val_custom
  const float* Wq_st = (const float*)d_in[6];   // W_query_charge_1  -> Q_st
  const float* Wk_s  = (const float*)d_in[7];   // W_key_charge
  const float* Wv_s  = (const float*)d_in[8];   // W_val_charge
  const float* Wout  = (const float*)d_in[9];
  float* out = (float*)d_out;

  int smem1 = (2*64*XSTR + 16*XSTR)*(int)sizeof(float);
  cudaFuncSetAttribute(k_proj, cudaFuncAttributeMaxDynamicSharedMemorySize, smem1);
  int smemA = (2*CHUNK*KSTR + 2*CHUNK*VSTR + 8*32*10)*(int)sizeof(float);
  cudaFuncSetAttribute(k_attn, cudaFuncAttributeMaxDynamicSharedMemorySize, smemA);
  int smem5 = (64*D_ + D_*132)*(int)sizeof(float);
  cudaFuncSetAttribute(k_out, cudaFuncAttributeMaxDynamicSharedMemorySize, smem5);

  k_proj<<<dim3(17, 32), 256, smem1>>>(q, h, Wq_tt, Wq_ts, Wk_c, Wv_c,
                                       Wq_st, Wk_s, Wv_s);
  k_attn<<<dim3(9, 32, 8), 256, smemA>>>();
  k_out<<<512, 256, smem5>>>(Wout, out);
}

// round 10
// speedup vs baseline: 1.7823x; 1.1552x over previous
#include <cuda_runtime.h>
#include <cstdint>

typedef unsigned long long ull;

#define B_   32
#define NH_  8
#define NN_  1024
#define NS_  21
#define NT_  1003
#define D_   128
#define KD_  16
#define HB_  (NH_*B_)

// NORM * log2(e) folded into query projections so softmax uses raw ex2.
#define QSCALE 0.36067376022224085f

#define CHUNK 128
#define KSTR  20    // K smem row stride (floats): conflict-free score-frag loads
#define VSTR  24    // V smem row stride (floats): conflict-free PV-frag loads
#define XSTR  132   // x smem row stride in proj
#define BSTR  132   // Wcat smem row stride in proj

// ---------------- scratch (device globals; no allocation allowed) ----------
__device__ float g_Qtt[HB_*NT_*KD_];
__device__ float g_Qts[HB_*NT_*KD_];
__device__ float g_Kc [HB_*NT_*KD_];
__device__ float g_Vc [HB_*NT_*KD_];
__device__ float g_Qst[HB_*NS_*KD_];
__device__ float g_Ks [HB_*NS_*KD_];
__device__ float g_Vs [HB_*NS_*KD_];
__device__ float g_heads[B_*NN_*NH_*KD_];   // layout [b][n][h][k]

// ---------------- helpers ---------------------------------------------------
__device__ __forceinline__ ull pack2(float lo, float hi){
  ull r; asm("mov.b64 %0, {%1,%2};" : "=l"(r) : "f"(lo), "f"(hi)); return r;
}
__device__ __forceinline__ void unpack2(ull v, float& lo, float& hi){
  asm("mov.b64 {%0,%1}, %2;" : "=f"(lo), "=f"(hi) : "l"(v));
}
__device__ __forceinline__ ull ffma2(ull a, ull b, ull c){
  ull d; asm("fma.rn.f32x2 %0, %1, %2, %3;" : "=l"(d) : "l"(a), "l"(b), "l"(c)); return d;
}
__device__ __forceinline__ float ex2f(float x){
  float r; asm("ex2.approx.f32 %0, %1;" : "=f"(r) : "f"(x)); return r;
}
__device__ __forceinline__ uint32_t tf32r(float f){
  uint32_t u; asm("cvt.rna.tf32.f32 %0, %1;" : "=r"(u) : "f"(f)); return u;
}
__device__ __forceinline__ float tf32rf(float f){ return __uint_as_float(tf32r(f)); }

__device__ __forceinline__ void cp_async16(void* s, const void* g){
  unsigned sa = (unsigned)__cvta_generic_to_shared(s);
  asm volatile("cp.async.cg.shared.global [%0], [%1], 16;" :: "r"(sa), "l"(g));
}
__device__ __forceinline__ void cp_commit(){ asm volatile("cp.async.commit_group;"); }
template<int N> __device__ __forceinline__ void cp_wait(){
  asm volatile("cp.async.wait_group %0;" :: "n"(N) : "memory");
}

// tf32 MMA: D(16x8) += A(16x8,row) * B(8x8,col)
__device__ __forceinline__ void mma8(float& d0, float& d1, float& d2, float& d3,
    uint32_t a0, uint32_t a1, uint32_t a2, uint32_t a3, uint32_t b0, uint32_t b1)
{
  asm("mma.sync.aligned.m16n8k8.row.col.f32.tf32.tf32.f32 "
      "{%0,%1,%2,%3},{%4,%5,%6,%7},{%8,%9},{%0,%1,%2,%3};"
      : "+f"(d0), "+f"(d1), "+f"(d2), "+f"(d3)
      : "r"(a0), "r"(a1), "r"(a2), "r"(a3), "r"(b0), "r"(b1));
}

// Load Q A-fragments for 2 k-steps (head_dim 16). rA,rB pre-clamped row indices.
__device__ __forceinline__ void loadQ(const float* Qb, int rA, int rB, int tig,
                                      uint32_t a[2][4])
{
  #pragma unroll
  for (int ks = 0; ks < 2; ks++){
    a[ks][0] = __float_as_uint(Qb[(size_t)rA*KD_ + tig     + 8*ks]);
    a[ks][1] = __float_as_uint(Qb[(size_t)rB*KD_ + tig     + 8*ks]);
    a[ks][2] = __float_as_uint(Qb[(size_t)rA*KD_ + tig + 4 + 8*ks]);
    a[ks][3] = __float_as_uint(Qb[(size_t)rB*KD_ + tig + 4 + 8*ks]);
  }
}

// One 8-key step: scores (2 MMA) -> exp -> (mask) -> P-frag shuffle ->
// ones-MMA row-sum (ls[0]=row g sum, ls[2]=row g+8 sum; fully reduced) ->
// P@V (2 MMA).
template<int MASK>
__device__ __forceinline__ void attn_step(
    const float* __restrict__ Ks, const float* __restrict__ Vs,
    const uint32_t (&aQ)[2][4], float (&o)[2][4], float (&ls)[4],
    int n8, int g, int tig, int lane, int nvalid)
{
  float c0 = 0.f, c1 = 0.f, c2 = 0.f, c3 = 0.f;
  const float* kp = Ks + (n8 + g)*KSTR + tig;
  {
    uint32_t b0 = __float_as_uint(kp[0]),  b1 = __float_as_uint(kp[4]);
    mma8(c0,c1,c2,c3, aQ[0][0],aQ[0][1],aQ[0][2],aQ[0][3], b0, b1);
    uint32_t b2 = __float_as_uint(kp[8]),  b3 = __float_as_uint(kp[12]);
    mma8(c0,c1,c2,c3, aQ[1][0],aQ[1][1],aQ[1][2],aQ[1][3], b2, b3);
  }
  float p0 = ex2f(c0), p1 = ex2f(c1), p2 = ex2f(c2), p3 = ex2f(c3);
  if (MASK){
    int col = n8 + tig*2;
    if (col     >= nvalid){ p0 = 0.f; p2 = 0.f; }
    if (col + 1 >= nvalid){ p1 = 0.f; p3 = 0.f; }
  }
  uint32_t u0 = tf32r(p0), u1 = tf32r(p1), u2 = tf32r(p2), u3 = tf32r(p3);
  // Rearrange D-frag (cols 2t,2t+1) into A-frag (cols t, t+4).
  int src  = (lane & 28) | (tig >> 1);
  int src2 = src + 2;
  uint32_t ev0 = __shfl_sync(0xffffffffu, u0, src ), od0 = __shfl_sync(0xffffffffu, u1, src );
  uint32_t ev1 = __shfl_sync(0xffffffffu, u2, src ), od1 = __shfl_sync(0xffffffffu, u3, src );
  uint32_t ev2 = __shfl_sync(0xffffffffu, u0, src2), od2 = __shfl_sync(0xffffffffu, u1, src2);
  uint32_t ev3 = __shfl_sync(0xffffffffu, u2, src2), od3 = __shfl_sync(0xffffffffu, u3, src2);
  bool odd = (tig & 1);
  uint32_t pa0 = odd ? od0 : ev0;
  uint32_t pa1 = odd ? od1 : ev1;
  uint32_t pa2 = odd ? od2 : ev2;
  uint32_t pa3 = odd ? od3 : ev3;
  const uint32_t one = 0x3f800000u;          // 1.0f (tf32-exact)
  mma8(ls[0], ls[1], ls[2], ls[3], pa0, pa1, pa2, pa3, one, one);
  #pragma unroll
  for (int nt = 0; nt < 2; nt++){
    uint32_t vb0 = __float_as_uint(Vs[(n8 + tig    )*VSTR + nt*8 + g]);
    uint32_t vb1 = __float_as_uint(Vs[(n8 + tig + 4)*VSTR + nt*8 + g]);
    mma8(o[nt][0], o[nt][1], o[nt][2], o[nt][3], pa0, pa1, pa2, pa3, vb0, vb1);
  }
}

// Cooperative chunk staging: 128 keys x 16 floats of K and V (256 threads).
__device__ __forceinline__ void stage_chunk(float* sKb, float* sVb,
    const float* __restrict__ Kg, const float* __restrict__ Vg, int kbase, int tid)
{
  #pragma unroll
  for (int i = 0; i < 2; i++){
    int f4  = tid + i*256;
    int row = f4 >> 2, qq = f4 & 3;
    int gr  = kbase + row;
    if (gr < NT_){
      cp_async16(sKb + row*KSTR + qq*4, Kg + (size_t)gr*KD_ + qq*4);
      cp_async16(sVb + row*VSTR + qq*4, Vg + (size_t)gr*KD_ + qq*4);
    }
  }
}

// ====================== Kernel 1: all projections ==========================
// blockIdx.x < 16 : token tile of 64 rows. Register-tiled fp32 f32x2 GEMM
//                   X[64,128] @ Wcat[128,128] per projection (Wcat = 8 heads
//                   concatenated). 4x8 outputs/thread: 3.4x less LDS traffic
//                   than the old scalar path (which was smem-BW bound at
//                   296us). Math still exact fp32 fma (tf32 proj FAILS: R7).
// blockIdx.x == 16: station projections (21 rows, scalar).
__global__ __launch_bounds__(256, 2) void k_proj(
    const float* __restrict__ q, const float* __restrict__ h,
    const float* __restrict__ Wqtt, const float* __restrict__ Wqts,
    const float* __restrict__ Wk, const float* __restrict__ Wv,
    const float* __restrict__ Wqst, const float* __restrict__ Wks,
    const float* __restrict__ Wvs)
{
  extern __shared__ float sm[];
  int b  = blockIdx.y;
  int tid = threadIdx.x;

  if (blockIdx.x == 16){
    // ---------------- station projections (scalar) ----------------
    float* sxq = sm;                 // 21*128
    float* sxh = sm + NS_*D_;
    float* sw  = sm + 2*NS_*D_;      // 128*16
    for (int idx = tid; idx < NS_*D_/4; idx += 256){
      int row = idx >> 5, d4 = idx & 31;
      size_t goff = ((size_t)(b*NN_ + row))*D_ + d4*4;
      ((float4*)sxq)[idx] = *(const float4*)(q + goff);
      ((float4*)sxh)[idx] = *(const float4*)(h + goff);
    }
    const float* Wp[3] = {Wqst, Wks, Wvs};
    for (int p = 0; p < 3; p++){
      const float* src = (p == 0) ? sxq : sxh;
      float scale = (p == 0) ? QSCALE : 1.0f;
      float* Dst = (p == 0) ? g_Qst : (p == 1 ? g_Ks : g_Vs);
      for (int hh = 0; hh < NH_; hh++){
        __syncthreads();
        const float* wp = Wp[p] + hh*D_*KD_;
        for (int idx = tid; idx < D_*KD_; idx += 256) sw[idx] = wp[idx]*scale;
        __syncthreads();
        for (int o = tid; o < NS_*KD_; o += 256){
          int s = o >> 4, k = o & 15;
          float a = 0.f;
          #pragma unroll 8
          for (int d = 0; d < D_; d++) a += src[s*D_ + d] * sw[d*KD_ + k];
          Dst[((size_t)(hh*B_ + b)*NS_ + s)*KD_ + k] = tf32rf(a);
        }
      }
    }
    return;
  }

  // ---------------- token projections: register-tiled GEMM ----------------
  float* sx = sm;                    // 64*XSTR   (x rows: q then h)
  float* sw = sm + 64*XSTR;          // 128*BSTR  (Wcat[d][hh*16+k], k-contig)

  int r0 = blockIdx.x * 64;
  int rg = tid >> 4, cg = tid & 15;            // 4-row group, 8-col group
  int hh = cg >> 1, khalf = (cg & 1)*8;

  const float* Xs[2] = {q, h};
  const float* Wp[4] = {Wqtt, Wqts, Wk, Wv};
  float* Dp[4]; Dp[0]=g_Qtt; Dp[1]=g_Qts; Dp[2]=g_Kc; Dp[3]=g_Vc;

  for (int ph = 0; ph < 2; ph++){
    const float* xs = Xs[ph];
    // load 64 token rows of x (row clamp; writes guarded later)
    #pragma unroll
    for (int i = 0; i < 8; i++){
      int idx = tid + i*256;
      int row = idx >> 5, d4 = idx & 31;
      int t = r0 + row; if (t > NT_-1) t = NT_-1;
      ((float4*)(sx + row*XSTR))[d4] =
          *(const float4*)(xs + ((size_t)(b*NN_ + NS_ + t))*D_ + d4*4);
    }
    for (int pp = 0; pp < 2; pp++){
      int p = ph*2 + pp;
      float scale = (p < 2) ? QSCALE : 1.0f;
      const float* wg = Wp[p];
      // stage Wcat: sw[d*BSTR + whh*16 + k] = W[whh][d][k]*scale (float4 loads)
      #pragma unroll
      for (int i = 0; i < 16; i++){
        int idx = tid + i*256;              // 4096 float4
        int d = idx & 127, hk = idx >> 7;   // hk = whh*4 + k4
        int whh = hk >> 2, k4 = hk & 3;
        float4 v = *(const float4*)(wg + whh*(D_*KD_) + d*KD_ + k4*4);
        v.x *= scale; v.y *= scale; v.z *= scale; v.w *= scale;
        *(float4*)(sw + d*BSTR + whh*16 + k4*4) = v;
      }
      __syncthreads();   // covers x load (pp==0) and W staging

      ull acc[4][4];
      #pragma unroll
      for (int i = 0; i < 4; i++)
        #pragma unroll
        for (int j = 0; j < 4; j++) acc[i][j] = 0ull;

      const float* Ab = sx + rg*4*XSTR;
      const float* Bb = sw + cg*8;
      #pragma unroll 2
      for (int kg = 0; kg < 32; kg++){
        float4 a[4];
        #pragma unroll
        for (int i = 0; i < 4; i++)
          a[i] = *(const float4*)(Ab + i*XSTR + kg*4);
        #pragma unroll
        for (int kk = 0; kk < 4; kk++){
          ulonglong2 bv0 = *(const ulonglong2*)(Bb + (kg*4 + kk)*BSTR);
          ulonglong2 bv1 = *(const ulonglong2*)(Bb + (kg*4 + kk)*BSTR + 4);
          #pragma unroll
          for (int i = 0; i < 4; i++){
            float av = (&a[i].x)[kk];
            ull ap = pack2(av, av);
            acc[i][0] = ffma2(ap, bv0.x, acc[i][0]);
            acc[i][1] = ffma2(ap, bv0.y, acc[i][1]);
            acc[i][2] = ffma2(ap, bv1.x, acc[i][2]);
            acc[i][3] = ffma2(ap, bv1.y, acc[i][3]);
          }
        }
      }

      float* dst = Dp[p] + ((size_t)(hh*B_ + b))*NT_*KD_ + khalf;
      #pragma unroll
      for (int i = 0; i < 4; i++){
        int t = r0 + rg*4 + i;
        if (t < NT_){
          float f0,f1,f2,f3,f4,f5,f6,f7;
          unpack2(acc[i][0], f0, f1);
          unpack2(acc[i][1], f2, f3);
          unpack2(acc[i][2], f4, f5);
          unpack2(acc[i][3], f6, f7);
          float4 v0 = make_float4(tf32rf(f0), tf32rf(f1), tf32rf(f2), tf32rf(f3));
          float4 v1 = make_float4(tf32rf(f4), tf32rf(f5), tf32rf(f6), tf32rf(f7));
          *(float4*)(dst + (size_t)t*KD_)     = v0;
          *(float4*)(dst + (size_t)t*KD_ + 4) = v1;
        }
      }
      __syncthreads();   // before sw (pp loop) or sx (ph loop) is overwritten
    }
  }
}

// ====================== Kernel 2: all attention ============================
// blockIdx.x < 8 : token-query path (128-query tile, warp = 16 q x all keys).
// blockIdx.x == 8: station-query path (warp = 16 q-rows x key stripe).
// No online max (QSCALE folds NORM*log2e; scores bounded, raw ex2 safe).
// Row sums fall out of the ones-MMA D-fragments already fully reduced.
__global__ __launch_bounds__(256) void k_attn()
{
  extern __shared__ float dsm[];
  float* sK0 = dsm;                                   // [2][128*KSTR]
  float* sV0 = dsm + 2*CHUNK*KSTR;                    // [2][128*VSTR]
  float* sKs = dsm + 2*CHUNK*KSTR + 2*CHUNK*VSTR;     // token: [24*KSTR]
  float* sVs = sKs + 24*KSTR;                         // token: [24*VSTR]
  float* red = dsm + 2*CHUNK*KSTR + 2*CHUNK*VSTR;     // station: [8*32*10]

  int b = blockIdx.y, hh = blockIdx.z;
  int tid = threadIdx.x;
  int w = tid >> 5, lane = tid & 31;
  int g = lane >> 2, tig = lane & 3;
  size_t hb = (size_t)(hh*B_ + b);
  const float* Kg = g_Kc + hb*NT_*KD_;
  const float* Vg = g_Vc + hb*NT_*KD_;
  const int nch = (NT_ + CHUNK - 1)/CHUNK;   // 8

  if (blockIdx.x < 8){
    // ======== token-query path ========
    int qrow = blockIdx.x * 128 + w*16;
    int rA = min(qrow + g,     NT_-1);
    int rB = min(qrow + g + 8, NT_-1);

    // zero station pad rows (21..23) so pad scores are finite then masked
    for (int i = tid; i < 3*KSTR; i += 256) sKs[21*KSTR + i] = 0.f;
    for (int i = tid; i < 3*VSTR; i += 256) sVs[21*VSTR + i] = 0.f;
    // group 1: station K/V
    if (tid < 96){
      int row = tid >> 2, qq = tid & 3;
      if (row < NS_){
        cp_async16(sKs + row*KSTR + qq*4, g_Ks + (hb*NS_ + row)*KD_ + qq*4);
        cp_async16(sVs + row*VSTR + qq*4, g_Vs + (hb*NS_ + row)*KD_ + qq*4);
      }
    }
    cp_commit();
    // group 2: token chunk 0
    stage_chunk(sK0, sV0, Kg, Vg, 0, tid);
    cp_commit();

    uint32_t aT[2][4];
    loadQ(g_Qtt + hb*NT_*KD_, rA, rB, tig, aT);

    // ---- station prologue: full mini-softmax, normalized into os ----
    float os[2][4] = {{0,0,0,0},{0,0,0,0}};
    {
      uint32_t aS[2][4];
      loadQ(g_Qts + hb*NT_*KD_, rA, rB, tig, aS);
      cp_wait<1>();          // group 1 (station) done
      __syncthreads();
      float lsS[4] = {0,0,0,0};
      attn_step<0>(sKs, sVs, aS, os, lsS, 0,  g, tig, lane, 0);
      attn_step<0>(sKs, sVs, aS, os, lsS, 8,  g, tig, lane, 0);
      attn_step<1>(sKs, sVs, aS, os, lsS, 16, g, tig, lane, NS_);
      float isa = 1.f/lsS[0], isb = 1.f/lsS[2];
      #pragma unroll
      for (int nt = 0; nt < 2; nt++){
        os[nt][0] *= isa; os[nt][1] *= isa;
        os[nt][2] *= isb; os[nt][3] *= isb;
      }
    }

    // ---- token mainloop ----
    float ot[2][4] = {{0,0,0,0},{0,0,0,0}};
    float ls[4] = {0,0,0,0};
    for (int c = 0; c < nch; c++){
      if (c + 1 < nch){
        int nb = (c+1) & 1;
        stage_chunk(sK0 + nb*CHUNK*KSTR, sV0 + nb*CHUNK*VSTR, Kg, Vg, (c+1)*CHUNK, tid);
        cp_commit();
        cp_wait<1>();
      } else {
        cp_wait<0>();
      }
      __syncthreads();
      const float* Ks = sK0 + (c&1)*CHUNK*KSTR;
      const float* Vs = sV0 + (c&1)*CHUNK*VSTR;
      int nv = min(CHUNK, NT_ - c*CHUNK);
      int nf = nv >> 3;
      #pragma unroll 4
      for (int n = 0; n < nf; n++)
        attn_step<0>(Ks, Vs, aT, ot, ls, n*8, g, tig, lane, 0);
      if (nv & 7)
        attn_step<1>(Ks, Vs, aT, ot, ls, nf*8, g, tig, lane, nv);
      __syncthreads();
    }

    float ita = 1.f/ls[0], itb = 1.f/ls[2];   // ones-MMA: already full row sums
    int row0 = qrow + g, row1 = qrow + g + 8;
    #pragma unroll
    for (int nt = 0; nt < 2; nt++){
      if (row0 < NT_){
        float2 v; v.x = ot[nt][0]*ita + os[nt][0];
                  v.y = ot[nt][1]*ita + os[nt][1];
        *(float2*)(g_heads + ((size_t)(b*NN_ + NS_ + row0)*NH_ + hh)*KD_ + nt*8 + 2*tig) = v;
      }
      if (row1 < NT_){
        float2 v; v.x = ot[nt][2]*itb + os[nt][2];
                  v.y = ot[nt][3]*itb + os[nt][3];
        *(float2*)(g_heads + ((size_t)(b*NN_ + NS_ + row1)*NH_ + hh)*KD_ + nt*8 + 2*tig) = v;
      }
    }
  } else {
    // ======== station-query path ========
    int rt = w & 1, s = w >> 1;        // 2 q-row-tiles x 4 key stripes
    int rA = min(rt*16 + g,     NS_-1);
    int rB = min(rt*16 + g + 8, NS_-1);
    uint32_t aQ[2][4];
    loadQ(g_Qst + hb*NS_*KD_, rA, rB, tig, aQ);

    float o[2][4] = {{0,0,0,0},{0,0,0,0}};
    float ls[4] = {0,0,0,0};

    stage_chunk(sK0, sV0, Kg, Vg, 0, tid);
    cp_commit();
    for (int c = 0; c < nch; c++){
      if (c + 1 < nch){
        int nb = (c+1) & 1;
        stage_chunk(sK0 + nb*CHUNK*KSTR, sV0 + nb*CHUNK*VSTR, Kg, Vg, (c+1)*CHUNK, tid);
        cp_commit();
        cp_wait<1>();
      } else {
        cp_wait<0>();
      }
      __syncthreads();
      const float* Ks = sK0 + (c&1)*CHUNK*KSTR;
      const float* Vs = sV0 + (c&1)*CHUNK*VSTR;
      int nv = min(CHUNK, NT_ - c*CHUNK);
      #pragma unroll
      for (int j = 0; j < 4; j++){
        int n8 = (s*4 + j)*8;
        if (n8 + 8 <= nv)
          attn_step<0>(Ks, Vs, aQ, o, ls, n8, g, tig, lane, 0);
        else if (n8 < nv)
          attn_step<1>(Ks, Vs, aQ, o, ls, n8, g, tig, lane, nv);
      }
      __syncthreads();
    }

    float* rp = red + (w*32 + lane)*10;
    rp[0]=o[0][0]; rp[1]=o[0][1]; rp[2]=o[0][2]; rp[3]=o[0][3];
    rp[4]=o[1][0]; rp[5]=o[1][1]; rp[6]=o[1][2]; rp[7]=o[1][3];
    rp[8]=ls[0]; rp[9]=ls[2];
    __syncthreads();
    if (w < 2){
      float la = ls[0], lb = ls[2];
      #pragma unroll
      for (int ss = 1; ss < 4; ss++){
        float* qp = red + ((w + 2*ss)*32 + lane)*10;
        o[0][0]+=qp[0]; o[0][1]+=qp[1]; o[0][2]+=qp[2]; o[0][3]+=qp[3];
        o[1][0]+=qp[4]; o[1][1]+=qp[5]; o[1][2]+=qp[6]; o[1][3]+=qp[7];
        la += qp[8]; lb += qp[9];
      }
      float ia = 1.f/la, ib = 1.f/lb;
      int r0 = rt*16 + g, r1 = r0 + 8;
      #pragma unroll
      for (int nt = 0; nt < 2; nt++){
        if (r0 < NS_){
          float2 v; v.x = o[nt][0]*ia; v.y = o[nt][1]*ia;
          *(float2*)(g_heads + ((size_t)(b*NN_ + r0)*NH_ + hh)*KD_ + nt*8 + 2*tig) = v;
        }
        if (r1 < NS_){
          float2 v; v.x = o[nt][2]*ib; v.y = o[nt][3]*ib;
          *(float2*)(g_heads + ((size_t)(b*NN_ + r1)*NH_ + hh)*KD_ + nt*8 + 2*tig) = v;
        }
      }
    }
  }
}

// ================ Kernel 3: output GEMM (fp32 f32x2, value path) ===========
__global__ __launch_bounds__(256, 2) void k_out(
    const float* __restrict__ Wout, float* __restrict__ out)
{
  extern __shared__ float sm[];
  float* sA  = sm;              // 64*128
  float* sWt = sm + 64*D_;      // 128*132 transposed
  int m0 = blockIdx.x * 64;
  int tid = threadIdx.x;
  for (int idx = tid; idx < 64*32; idx += 256){
    int r = idx >> 5, d4 = idx & 31;
    ((float4*)(sA + r*D_))[d4] = ((const float4*)(g_heads + (size_t)(m0 + r)*D_))[d4];
  }
  for (int idx = tid; idx < D_*D_; idx += 256){
    int c = idx >> 7, e = idx & 127;
    sWt[e*132 + c] = Wout[idx];
  }
  __syncthreads();
  int rg = tid >> 4, cg = tid & 15;
  ull acc2[4][8];
  #pragma unroll
  for (int i = 0; i < 4; i++)
    #pragma unroll
    for (int e = 0; e < 8; e++) acc2[i][e] = 0ull;
  #pragma unroll 2
  for (int d4 = 0; d4 < 32; d4++){
    ulonglong2 a[4];
    #pragma unroll
    for (int i = 0; i < 4; i++)
      a[i] = *(const ulonglong2*)(sA + (rg*4 + i)*D_ + d4*4);
    #pragma unroll
    for (int e = 0; e < 8; e++){
      ulonglong2 wv = *(const ulonglong2*)(sWt + (cg*8 + e)*132 + d4*4);
      #pragma unroll
      for (int i = 0; i < 4; i++){
        acc2[i][e] = ffma2(a[i].x, wv.x, acc2[i][e]);
        acc2[i][e] = ffma2(a[i].y, wv.y, acc2[i][e]);
      }
    }
  }
  #pragma unroll
  for (int i = 0; i < 4; i++){
    #pragma unroll
    for (int e = 0; e < 8; e++){
      float lo, hi; unpack2(acc2[i][e], lo, hi);
      out[(size_t)(m0 + rg*4 + i)*D_ + cg*8 + e] = lo + hi;
    }
  }
}

// ===========================================================================
extern "C" void kernel_launch(void* const* d_in, const int* in_sizes, int n_in,
                              void* d_out, int out_size)
{
  const float* q     = (const float*)d_in[0];
  const float* h     = (const float*)d_in[1];
  const float* Wq_ts = (const float*)d_in[2];   // W_query_custom    -> Q_ts
  const float* Wq_tt = (const float*)d_in[3];   // W_query_custom_1  -> Q_tt
  const float* Wk_c  = (const float*)d_in[4];   // W_key_custom
  const float* Wv_c  = (const float*)d_in[5];   // W_val_custom
  const float* Wq_st = (const float*)d_in[6];   // W_query_charge_1  -> Q_st
  const float* Wk_s  = (const float*)d_in[7];   // W_key_charge
  const float* Wv_s  = (const float*)d_in[8];   // W_val_charge
  const float* Wout  = (const float*)d_in[9];
  float* out = (float*)d_out;

  int smem1 = (64*XSTR + 128*BSTR)*(int)sizeof(float);   // 101376 B
  cudaFuncSetAttribute(k_proj, cudaFuncAttributeMaxDynamicSharedMemorySize, smem1);
  int smemA = (2*CHUNK*KSTR + 2*CHUNK*VSTR + 8*32*10)*(int)sizeof(float);
  cudaFuncSetAttribute(k_attn, cudaFuncAttributeMaxDynamicSharedMemorySize, smemA);
  int smem5 = (64*D_ + D_*132)*(int)sizeof(float);
  cudaFuncSetAttribute(k_out, cudaFuncAttributeMaxDynamicSharedMemorySize, smem5);

  k_proj<<<dim3(17, 32), 256, smem1>>>(q, h, Wq_tt, Wq_ts, Wk_c, Wv_c,
                                       Wq_st, Wk_s, Wv_s);
  k_attn<<<dim3(9, 32, 8), 256, smemA>>>();
  k_out<<<512, 256, smem5>>>(Wout, out);
}